// round 9
// baseline (speedup 1.0000x reference)
#include <cuda_runtime.h>
#include <cuda_bf16.h>
#include <math.h>
#include <stdint.h>

#define DIMC 2560
#define BB 2
#define SS 2048
#define SCC 512
#define HH 20
#define HDD 128
#define FFNN 10240
#define EPSF 1e-6f
#define ROWS (BB*SS)      /* 4096 */
#define ROWSC (BB*SCC)    /* 1024 */

typedef __nv_bfloat16 bf16;
typedef __nv_bfloat162 bf162;

// ---------------- scratch (device globals) ----------------
__device__ float g_qkv[(size_t)ROWS*3*DIMC];
__device__ float g_q  [(size_t)ROWS*DIMC];
__device__ float g_h  [(size_t)ROWS*DIMC];
__device__ float g_kv [(size_t)ROWSC*2*DIMC];
__device__ float g_x  [(size_t)ROWS*DIMC];     // tf32-permuted LN output
__device__ float g_ao [(size_t)ROWS*DIMC];     // tf32-permuted attention output
__device__ float g_f  [(size_t)ROWS*FFNN];     // tf32-permuted gelu output
__device__ float g_enc[(size_t)ROWSC*DIMC];    // tf32-permuted encoder states
__device__ float g_wt0[(size_t)3*DIMC*DIMC];
__device__ float g_wt1[(size_t)DIMC*DIMC];
__device__ float g_wt2[(size_t)DIMC*DIMC];
__device__ float g_wt3[(size_t)2*DIMC*DIMC];
__device__ float g_wt4[(size_t)DIMC*DIMC];
__device__ float g_wt5[(size_t)FFNN*DIMC];
__device__ float g_wt6[(size_t)DIMC*FFNN];
__device__ bf16 g_qah[(size_t)ROWS*DIMC], g_qal[(size_t)ROWS*DIMC];
__device__ bf16 g_kah[(size_t)ROWS*DIMC], g_kal[(size_t)ROWS*DIMC];
__device__ bf16 g_vth[(size_t)BB*HH*HDD*SS], g_vtl[(size_t)BB*HH*HDD*SS];

// ---------------- helpers ----------------
__device__ __forceinline__ void cp_async16(uint32_t saddr, const void* gaddr){
    asm volatile("cp.async.cg.shared.global [%0], [%1], 16;" :: "r"(saddr), "l"(gaddr));
}
__device__ __forceinline__ void cp_commit(){ asm volatile("cp.async.commit_group;" ::: "memory"); }
__device__ __forceinline__ uint32_t smem_u32(const void* p){
    uint32_t a; asm("{ .reg .u64 t; cvta.to.shared.u64 t, %1; cvt.u32.u64 %0, t; }" : "=r"(a) : "l"(p)); return a;
}
__device__ __forceinline__ void mma16816(float* d, const uint32_t* a, const uint32_t* b){
    asm volatile("mma.sync.aligned.m16n8k16.row.col.f32.bf16.bf16.f32 "
        "{%0,%1,%2,%3}, {%4,%5,%6,%7}, {%8,%9}, {%0,%1,%2,%3};"
        : "+f"(d[0]), "+f"(d[1]), "+f"(d[2]), "+f"(d[3])
        : "r"(a[0]), "r"(a[1]), "r"(a[2]), "r"(a[3]), "r"(b[0]), "r"(b[1]));
}
__device__ __forceinline__ void mma_tf32(float* d, const uint32_t* a, const uint32_t* b){
    asm volatile("mma.sync.aligned.m16n8k8.row.col.f32.tf32.tf32.f32 "
        "{%0,%1,%2,%3}, {%4,%5,%6,%7}, {%8,%9}, {%0,%1,%2,%3};"
        : "+f"(d[0]), "+f"(d[1]), "+f"(d[2]), "+f"(d[3])
        : "r"(a[0]), "r"(a[1]), "r"(a[2]), "r"(a[3]), "r"(b[0]), "r"(b[1]));
}
__device__ __forceinline__ void ldmatrix_x4(uint32_t* r, uint32_t addr){
    asm volatile("ldmatrix.sync.aligned.m8n8.x4.shared.b16 {%0,%1,%2,%3}, [%4];"
        : "=r"(r[0]), "=r"(r[1]), "=r"(r[2]), "=r"(r[3]) : "r"(addr));
}
__device__ __forceinline__ void lds128(uint32_t* r, uint32_t addr){
    asm volatile("ld.shared.v4.b32 {%0,%1,%2,%3}, [%4];"
        : "=r"(r[0]), "=r"(r[1]), "=r"(r[2]), "=r"(r[3]) : "r"(addr));
}
__device__ __forceinline__ float ex2f(float x){
    float y; asm("ex2.approx.f32 %0, %1;" : "=f"(y) : "f"(x)); return y;
}
__device__ __forceinline__ uint32_t pack_bf16(float a, float b){
    bf162 t; t.x = __float2bfloat16(a); t.y = __float2bfloat16(b);
    return *(uint32_t*)&t;
}
__device__ __forceinline__ float gelu_tanh(float u){
    return 0.5f * u * (1.f + tanhf(0.7978845608028654f * (u + 0.044715f * u * u * u)));
}
__device__ __forceinline__ float tf32r(float x){
    uint32_t u; asm("cvt.rna.tf32.f32 %0, %1;" : "=r"(u) : "f"(x));
    return __uint_as_float(u);
}
// K-permutation within each 32-element block: contiguous 8-word fragment runs
__device__ __forceinline__ int permc(int c){
    return (c & ~31) | ((c & 3) << 3) | ((c & 31) >> 2);
}

// ---------------- weight/encoder convert: f32 -> tf32-rounded, K-permuted ---
__global__ __launch_bounds__(256) void convert_kernel(
    const float* __restrict__ src, float* __restrict__ dst, int K)
{
    const float* s = src + (size_t)blockIdx.x * K;
    float* d = dst + (size_t)blockIdx.x * K;
    for (int c = threadIdx.x; c < K; c += 256)
        d[permc(c)] = tf32r(s[c]);
}

// ---------------- LayerNorm -> tf32-permuted f32 ----------------
__global__ __launch_bounds__(256) void ln_kernel(
    const float* __restrict__ x, float* __restrict__ o,
    const float* __restrict__ gamma, const float* __restrict__ beta,
    const float* __restrict__ sst, const float* __restrict__ temb,
    int shift_idx, int scale_idx, int S)
{
    int row = blockIdx.x;
    int b = row / S;
    const float* xr = x + (size_t)row * DIMC;
    float vals[10];
    float s1 = 0.f, s2 = 0.f;
#pragma unroll
    for (int i = 0; i < 10; ++i) {
        float v = xr[threadIdx.x + i * 256];
        vals[i] = v; s1 += v; s2 += v * v;
    }
#pragma unroll
    for (int o2 = 16; o2 > 0; o2 >>= 1) {
        s1 += __shfl_xor_sync(0xffffffffu, s1, o2);
        s2 += __shfl_xor_sync(0xffffffffu, s2, o2);
    }
    __shared__ float red[16];
    int wid = threadIdx.x >> 5;
    if ((threadIdx.x & 31) == 0) { red[wid] = s1; red[8 + wid] = s2; }
    __syncthreads();
    float ts = 0.f, tq = 0.f;
#pragma unroll
    for (int i = 0; i < 8; ++i) { ts += red[i]; tq += red[8 + i]; }
    float mean = ts * (1.f / DIMC);
    float var  = tq * (1.f / DIMC) - mean * mean;
    float inv  = rsqrtf(var + EPSF);
    size_t ro = (size_t)row * DIMC;
#pragma unroll
    for (int i = 0; i < 10; ++i) {
        int c = threadIdx.x + i * 256;
        float y = (vals[i] - mean) * inv;
        if (sst) {
            float scv = sst[scale_idx * DIMC + c] + temb[((size_t)b * 6 + scale_idx) * DIMC + c];
            float shv = sst[shift_idx * DIMC + c] + temb[((size_t)b * 6 + shift_idx) * DIMC + c];
            y = y * (1.f + scv) + shv;
        } else if (gamma) {
            y = y * gamma[c] + beta[c];
        }
        o[ro + permc(c)] = tf32r(y);
    }
}

// ---------------- RMSNorm + RoPE -> bf16 hi/lo (scaled; attention input) ----
__global__ __launch_bounds__(256) void rmsrope_kernel(
    const float* __restrict__ in, int istride, int ioff,
    bf16* __restrict__ ohi, bf16* __restrict__ olo, const float* __restrict__ w,
    const float* __restrict__ cosT, const float* __restrict__ sinT, int S, float scale)
{
    int row = blockIdx.x;
    int s = row % S;
    const float* xr = in + (size_t)row * istride + ioff;
    float vals[10];
    float sq = 0.f;
#pragma unroll
    for (int i = 0; i < 10; ++i) {
        float v = xr[threadIdx.x + i * 256];
        vals[i] = v; sq += v * v;
    }
#pragma unroll
    for (int o = 16; o > 0; o >>= 1) sq += __shfl_xor_sync(0xffffffffu, sq, o);
    __shared__ float red[8];
    int wid = threadIdx.x >> 5;
    if ((threadIdx.x & 31) == 0) red[wid] = sq;
    __syncthreads();
    float tq = 0.f;
#pragma unroll
    for (int i = 0; i < 8; ++i) tq += red[i];
    float inv = rsqrtf(tq * (1.f / DIMC) + EPSF);
    size_t ro = (size_t)row * DIMC;
#pragma unroll
    for (int i = 0; i < 10; ++i) {
        int c = threadIdx.x + i * 256;
        int d = c & (HDD - 1);
        int pc = (d < 64) ? c + 64 : c - 64;
        float y  = vals[i] * inv * w[c];
        float py = xr[pc]  * inv * w[pc];
        float cv = cosT[(size_t)s * HDD + d];
        float sv = sinT[(size_t)s * HDD + d];
        float val = (y * cv + ((d < 64) ? -py : py) * sv) * scale;
        bf16 h = __float2bfloat16(val);
        ohi[ro + c] = h;
        olo[ro + c] = __float2bfloat16(val - __bfloat162float(h));
    }
}

// ---------------- RMSNorm -> bf16 hi/lo (scaled) ----------------
__global__ __launch_bounds__(256) void rms_out_kernel(
    const float* __restrict__ in, int istride, int ioff,
    bf16* __restrict__ ohi, bf16* __restrict__ olo,
    const float* __restrict__ w, float scale)
{
    int row = blockIdx.x;
    const float* xr = in + (size_t)row * istride + ioff;
    float vals[10];
    float sq = 0.f;
#pragma unroll
    for (int i = 0; i < 10; ++i) {
        float v = xr[threadIdx.x + i * 256];
        vals[i] = v; sq += v * v;
    }
#pragma unroll
    for (int o = 16; o > 0; o >>= 1) sq += __shfl_xor_sync(0xffffffffu, sq, o);
    __shared__ float red[8];
    int wid = threadIdx.x >> 5;
    if ((threadIdx.x & 31) == 0) red[wid] = sq;
    __syncthreads();
    float tq = 0.f;
#pragma unroll
    for (int i = 0; i < 8; ++i) tq += red[i];
    float inv = rsqrtf(tq * (1.f / DIMC) + EPSF);
    size_t ro = (size_t)row * DIMC;
#pragma unroll
    for (int i = 0; i < 10; ++i) {
        int c = threadIdx.x + i * 256;
        float val = vals[i] * inv * w[c] * scale;
        bf16 h = __float2bfloat16(val);
        ohi[ro + c] = h;
        olo[ro + c] = __float2bfloat16(val - __bfloat162float(h));
    }
}

// ---------------- V transpose: f32 -> bf16 hi/lo [b,h,d,s] ------------------
__global__ __launch_bounds__(256) void vtrans_kernel(
    const float* __restrict__ in, int istride, int ioff,
    bf16* __restrict__ ohi, bf16* __restrict__ olo, int Skv)
{
    __shared__ float tile[32 * 129];
    int s0 = blockIdx.x * 32;
    int h  = blockIdx.y;
    int b  = blockIdx.z;
    int tid = threadIdx.x;
#pragma unroll
    for (int i = 0; i < 16; ++i) {
        int id = i * 256 + tid;
        int s = id >> 7, d = id & 127;
        tile[s * 129 + d] = in[(size_t)(b * Skv + s0 + s) * istride + ioff + h * HDD + d];
    }
    __syncthreads();
#pragma unroll
    for (int i = 0; i < 16; ++i) {
        int id = i * 256 + tid;
        int d = id >> 5, s = id & 31;
        float v = tile[s * 129 + d];
        bf16 hh = __float2bfloat16(v);
        size_t o = ((size_t)((b * HH + h) * HDD + d)) * Skv + s0 + s;
        ohi[o] = hh;
        olo[o] = __float2bfloat16(v - __bfloat162float(hh));
    }
}

// ---------------- TF32 single-pass GEMM (128x128 CTA, 64x64 warp tiles) -----
// 2-stage cp.async pipeline, 3 CTAs/SM. pitch 144B -> conflict-free LDS.128.
#define GPITCH 144
#define GTILEB (128 * GPITCH)            /* 18432 */
#define GSTAGEB (2 * GTILEB)             /* 36864 */
#define GEMM_SMEM (2 * GSTAGEB)          /* 73728 */

__global__ __launch_bounds__(128, 3) void gemm_tf32(
    const float* __restrict__ A, const float* __restrict__ B,
    const float* __restrict__ bias,
    float* __restrict__ C, float* __restrict__ Cp,
    int N, int K, int mode,
    const float* __restrict__ res, const float* __restrict__ sst,
    const float* __restrict__ temb, int gate_idx, int rows_per_batch)
{
    extern __shared__ char smem[];
    const uint32_t sb = smem_u32(smem);
    const int tid = threadIdx.x;
    const int wid = tid >> 5, lane = tid & 31;
    const int wm = wid & 1, wn = wid >> 1;      // 2x2 warp grid, warp = 64x64
    const int g = lane >> 2, tig = lane & 3;
    const int mt = blockIdx.x, nt = blockIdx.y;

    const int NIT = K >> 5;
    const char* Ag = (const char*)(A + (size_t)mt * 128 * K);
    const char* Bg = (const char*)(B + (size_t)nt * 128 * K);
    const size_t grb = (size_t)K * 4;

    auto load_tile = [&](int kc, int buf) {
        uint32_t s0 = sb + (uint32_t)buf * GSTAGEB;
        const char* a0 = Ag + (size_t)kc * 128;
        const char* b0 = Bg + (size_t)kc * 128;
#pragma unroll
        for (int i = 0; i < 8; ++i) {
            int idx = i * 128 + tid;
            int r = idx >> 3, c = idx & 7;
            cp_async16(s0 + (uint32_t)(r * GPITCH + c * 16), a0 + (size_t)r * grb + c * 16);
        }
#pragma unroll
        for (int i = 0; i < 8; ++i) {
            int idx = i * 128 + tid;
            int r = idx >> 3, c = idx & 7;
            cp_async16(s0 + GTILEB + (uint32_t)(r * GPITCH + c * 16), b0 + (size_t)r * grb + c * 16);
        }
        cp_commit();
    };

    load_tile(0, 0);

    float acc[4][8][4];
#pragma unroll
    for (int mi = 0; mi < 4; ++mi)
#pragma unroll
        for (int ni = 0; ni < 8; ++ni)
#pragma unroll
            for (int j = 0; j < 4; ++j) acc[mi][ni][j] = 0.f;

    const uint32_t aL = (uint32_t)((wm * 64 + g) * GPITCH + tig * 32);
    const uint32_t bL = (uint32_t)((wn * 64 + g) * GPITCH + tig * 32);

    for (int it = 0; it < NIT; ++it) {
        asm volatile("cp.async.wait_group 0;" ::: "memory");
        __syncthreads();
        if (it + 1 < NIT) load_tile(it + 1, (it + 1) & 1);

        uint32_t su = sb + (uint32_t)(it & 1) * GSTAGEB;
        uint32_t sA = su + aL;
        uint32_t sB = su + GTILEB + bL;
        // two k16 halves; per half, B in two groups of 4 n-rows (register diet)
#pragma unroll
        for (int h2 = 0; h2 < 2; ++h2) {
            uint32_t off = (uint32_t)(h2 * 16);
#pragma unroll
            for (int bg = 0; bg < 2; ++bg) {
                uint32_t bm[4][4];
#pragma unroll
                for (int nj = 0; nj < 4; ++nj)
                    lds128(&bm[nj][0], sB + (uint32_t)((bg * 4 + nj) * 8 * GPITCH) + off);
#pragma unroll
                for (int mi = 0; mi < 4; ++mi) {
                    uint32_t am[8];
                    lds128(&am[0], sA + (uint32_t)(mi * 16 * GPITCH) + off);
                    lds128(&am[4], sA + (uint32_t)((mi * 16 + 8) * GPITCH) + off);
                    uint32_t afL[4] = {am[0], am[4], am[1], am[5]};
                    uint32_t afH[4] = {am[2], am[6], am[3], am[7]};
#pragma unroll
                    for (int nj = 0; nj < 4; ++nj) {
                        mma_tf32(acc[mi][bg * 4 + nj], afL, &bm[nj][0]);
                        mma_tf32(acc[mi][bg * 4 + nj], afH, &bm[nj][2]);
                    }
                }
            }
        }
    }

    // ---- epilogue ----
#pragma unroll
    for (int mi = 0; mi < 4; ++mi) {
#pragma unroll
        for (int half = 0; half < 2; ++half) {
            int m = mt * 128 + wm * 64 + mi * 16 + g + half * 8;
            size_t rowb = (size_t)m * N;
#pragma unroll
            for (int ni = 0; ni < 8; ++ni) {
                int n = nt * 128 + wn * 64 + ni * 8 + tig * 2;
                float v0 = acc[mi][ni][half * 2 + 0] + bias[n];
                float v1 = acc[mi][ni][half * 2 + 1] + bias[n + 1];
                if (mode == 3) {
                    int p = permc(n);
                    Cp[rowb + p]     = tf32r(gelu_tanh(v0));
                    Cp[rowb + p + 8] = tf32r(gelu_tanh(v1));
                } else if (mode == 2) {
                    int bb = m / rows_per_batch;
                    float g0 = sst[(size_t)gate_idx * N + n]     + temb[((size_t)bb * 6 + gate_idx) * N + n];
                    float g1 = sst[(size_t)gate_idx * N + n + 1] + temb[((size_t)bb * 6 + gate_idx) * N + n + 1];
                    float2 rv = *(const float2*)(res + rowb + n);
                    float2 w; w.x = rv.x + g0 * v0; w.y = rv.y + g1 * v1;
                    *(float2*)(C + rowb + n) = w;
                } else if (mode == 1) {
                    float2 rv = *(const float2*)(res + rowb + n);
                    float2 w; w.x = rv.x + v0; w.y = rv.y + v1;
                    *(float2*)(C + rowb + n) = w;
                } else {
                    float2 w; w.x = v0; w.y = v1;
                    *(float2*)(C + rowb + n) = w;
                }
            }
        }
    }
}

// ---------------- mma flash attention (split-bf16, 3-term) -----------------
// Output: tf32-rounded, K-permuted f32 (feeds the o-projection GEMMs).
#define AKH 0
#define AKL 17408
#define AVH 34816
#define AVL 53248
#define ASTG 71680
#define ATT_SMEM (2 * ASTG)   /* 143360 */

__global__ __launch_bounds__(256) void attn_mma(
    const bf16* __restrict__ qh, const bf16* __restrict__ ql,
    const bf16* __restrict__ kh, const bf16* __restrict__ kl,
    const bf16* __restrict__ vth, const bf16* __restrict__ vtl,
    float* __restrict__ O,
    int S, int Skv)
{
    extern __shared__ char sm[];
    const uint32_t sb = smem_u32(sm);
    const int tid = threadIdx.x;
    const int wid = tid >> 5, lane = tid & 31;
    const int g = lane >> 2, tig = lane & 3;
    const int h = blockIdx.y, b = blockIdx.z;
    const int q0 = blockIdx.x * 128 + wid * 16;

    const bf16* qbh = qh + ((size_t)(b * S + q0 + g) * DIMC + h * HDD + tig * 2);
    const bf16* qbl = ql + ((size_t)(b * S + q0 + g) * DIMC + h * HDD + tig * 2);
    uint32_t qfh[8][4], qfl[8][4];
#pragma unroll
    for (int kc = 0; kc < 8; ++kc) {
        qfh[kc][0] = *(const uint32_t*)(qbh + kc * 16);
        qfh[kc][1] = *(const uint32_t*)(qbh + 8 * DIMC + kc * 16);
        qfh[kc][2] = *(const uint32_t*)(qbh + kc * 16 + 8);
        qfh[kc][3] = *(const uint32_t*)(qbh + 8 * DIMC + kc * 16 + 8);
        qfl[kc][0] = *(const uint32_t*)(qbl + kc * 16);
        qfl[kc][1] = *(const uint32_t*)(qbl + 8 * DIMC + kc * 16);
        qfl[kc][2] = *(const uint32_t*)(qbl + kc * 16 + 8);
        qfl[kc][3] = *(const uint32_t*)(qbl + 8 * DIMC + kc * 16 + 8);
    }

    float oacc[16][4];
#pragma unroll
    for (int j = 0; j < 16; ++j)
#pragma unroll
        for (int i = 0; i < 4; ++i) oacc[j][i] = 0.f;
    float mrow0 = -1e30f, mrow1 = -1e30f, lrow0 = 0.f, lrow1 = 0.f;

    const int nkt = Skv >> 6;

    auto stage = [&](int t) {
        uint32_t s0 = sb + (uint32_t)(t & 1) * ASTG;
        const char* kgh = (const char*)(kh + ((size_t)(b * Skv + t * 64) * DIMC + h * HDD));
        const char* kgl = (const char*)(kl + ((size_t)(b * Skv + t * 64) * DIMC + h * HDD));
#pragma unroll
        for (int i = 0; i < 4; ++i) {
            int id = i * 256 + tid;
            int r = id >> 4, c = id & 15;
            cp_async16(s0 + AKH + (uint32_t)(r * 272 + c * 16), kgh + (size_t)r * DIMC * 2 + c * 16);
        }
#pragma unroll
        for (int i = 0; i < 4; ++i) {
            int id = i * 256 + tid;
            int r = id >> 4, c = id & 15;
            cp_async16(s0 + AKL + (uint32_t)(r * 272 + c * 16), kgl + (size_t)r * DIMC * 2 + c * 16);
        }
        const char* vgh = (const char*)(vth + ((size_t)((b * HH + h) * HDD) * Skv + t * 64));
        const char* vgl = (const char*)(vtl + ((size_t)((b * HH + h) * HDD) * Skv + t * 64));
#pragma unroll
        for (int i = 0; i < 4; ++i) {
            int id = i * 256 + tid;
            int r = id >> 3, c = id & 7;
            cp_async16(s0 + AVH + (uint32_t)(r * 144 + c * 16), vgh + (size_t)r * Skv * 2 + c * 16);
        }
#pragma unroll
        for (int i = 0; i < 4; ++i) {
            int id = i * 256 + tid;
            int r = id >> 3, c = id & 7;
            cp_async16(s0 + AVL + (uint32_t)(r * 144 + c * 16), vgl + (size_t)r * Skv * 2 + c * 16);
        }
        cp_commit();
    };

    const uint32_t bk_lane = (uint32_t)(((lane & 7) + ((lane >> 4) << 3)) * 272 + (((lane >> 3) & 1) << 4));
    const uint32_t bv_lane = (uint32_t)(((lane & 7) + ((lane >> 4) << 3)) * 144 + (((lane >> 3) & 1) << 4));

    stage(0);
    asm volatile("cp.async.wait_group 0;" ::: "memory");
    __syncthreads();

    for (int t = 0; t < nkt; ++t) {
        bool more = (t + 1 < nkt);
        if (more) stage(t + 1);

        uint32_t kb = sb + (uint32_t)(t & 1) * ASTG;

        float sacc[8][4];
#pragma unroll
        for (int j = 0; j < 8; ++j)
#pragma unroll
            for (int i = 0; i < 4; ++i) sacc[j][i] = 0.f;
#pragma unroll
        for (int kc = 0; kc < 8; ++kc) {
#pragma unroll
            for (int j2 = 0; j2 < 4; ++j2) {
                uint32_t bh[4], bl[4];
                ldmatrix_x4(bh, kb + AKH + (uint32_t)(j2 * 16 * 272) + (uint32_t)(kc * 32) + bk_lane);
                ldmatrix_x4(bl, kb + AKL + (uint32_t)(j2 * 16 * 272) + (uint32_t)(kc * 32) + bk_lane);
                mma16816(sacc[2 * j2],     qfh[kc], &bh[0]);
                mma16816(sacc[2 * j2],     qfl[kc], &bh[0]);
                mma16816(sacc[2 * j2],     qfh[kc], &bl[0]);
                mma16816(sacc[2 * j2 + 1], qfh[kc], &bh[2]);
                mma16816(sacc[2 * j2 + 1], qfl[kc], &bh[2]);
                mma16816(sacc[2 * j2 + 1], qfh[kc], &bl[2]);
            }
        }

        float mx0 = -1e30f, mx1 = -1e30f;
#pragma unroll
        for (int j = 0; j < 8; ++j) {
            mx0 = fmaxf(mx0, fmaxf(sacc[j][0], sacc[j][1]));
            mx1 = fmaxf(mx1, fmaxf(sacc[j][2], sacc[j][3]));
        }
        mx0 = fmaxf(mx0, __shfl_xor_sync(0xffffffffu, mx0, 1));
        mx0 = fmaxf(mx0, __shfl_xor_sync(0xffffffffu, mx0, 2));
        mx1 = fmaxf(mx1, __shfl_xor_sync(0xffffffffu, mx1, 1));
        mx1 = fmaxf(mx1, __shfl_xor_sync(0xffffffffu, mx1, 2));
        float mn0 = fmaxf(mrow0, mx0), mn1 = fmaxf(mrow1, mx1);
        float cr0 = ex2f(mrow0 - mn0), cr1 = ex2f(mrow1 - mn1);
        mrow0 = mn0; mrow1 = mn1;
        lrow0 *= cr0; lrow1 *= cr1;
#pragma unroll
        for (int j = 0; j < 16; ++j) {
            oacc[j][0] *= cr0; oacc[j][1] *= cr0;
            oacc[j][2] *= cr1; oacc[j][3] *= cr1;
        }
        float ls0 = 0.f, ls1 = 0.f;
        uint32_t pah[4][4], pal[4][4];
#pragma unroll
        for (int j = 0; j < 8; ++j) {
            float p0 = ex2f(sacc[j][0] - mn0);
            float p1 = ex2f(sacc[j][1] - mn0);
            float p2 = ex2f(sacc[j][2] - mn1);
            float p3 = ex2f(sacc[j][3] - mn1);
            ls0 += p0 + p1; ls1 += p2 + p3;
            float h0 = __bfloat162float(__float2bfloat16(p0));
            float h1 = __bfloat162float(__float2bfloat16(p1));
            float h2 = __bfloat162float(__float2bfloat16(p2));
            float h3 = __bfloat162float(__float2bfloat16(p3));
            int kt = j >> 1, sl = (j & 1) * 2;
            pah[kt][sl + 0] = pack_bf16(h0, h1);
            pah[kt][sl + 1] = pack_bf16(h2, h3);
            pal[kt][sl + 0] = pack_bf16(p0 - h0, p1 - h1);
            pal[kt][sl + 1] = pack_bf16(p2 - h2, p3 - h3);
        }
        ls0 += __shfl_xor_sync(0xffffffffu, ls0, 1);
        ls0 += __shfl_xor_sync(0xffffffffu, ls0, 2);
        ls1 += __shfl_xor_sync(0xffffffffu, ls1, 1);
        ls1 += __shfl_xor_sync(0xffffffffu, ls1, 2);
        lrow0 += ls0; lrow1 += ls1;

#pragma unroll
        for (int kt = 0; kt < 4; ++kt) {
#pragma unroll
            for (int jd2 = 0; jd2 < 8; ++jd2) {
                uint32_t bh[4], bl[4];
                ldmatrix_x4(bh, kb + AVH + (uint32_t)(jd2 * 16 * 144) + (uint32_t)(kt * 32) + bv_lane);
                ldmatrix_x4(bl, kb + AVL + (uint32_t)(jd2 * 16 * 144) + (uint32_t)(kt * 32) + bv_lane);
                mma16816(oacc[2 * jd2],     pah[kt], &bh[0]);
                mma16816(oacc[2 * jd2],     pal[kt], &bh[0]);
                mma16816(oacc[2 * jd2],     pah[kt], &bl[0]);
                mma16816(oacc[2 * jd2 + 1], pah[kt], &bh[2]);
                mma16816(oacc[2 * jd2 + 1], pal[kt], &bh[2]);
                mma16816(oacc[2 * jd2 + 1], pah[kt], &bl[2]);
            }
        }

        if (more) { asm volatile("cp.async.wait_group 0;" ::: "memory"); }
        __syncthreads();
    }

    // ---- normalize + write tf32-permuted f32 ----
    float inv0 = 1.f / lrow0, inv1 = 1.f / lrow1;
    size_t r0 = (size_t)(b * S + q0 + g) * DIMC;
    size_t r1 = r0 + 8 * DIMC;
    int cbase = h * HDD + tig * 2;
#pragma unroll
    for (int j = 0; j < 16; ++j) {
        int c = cbase + j * 8;
        int p = permc(c);
        O[r0 + p]     = tf32r(oacc[j][0] * inv0);
        O[r0 + p + 8] = tf32r(oacc[j][1] * inv0);
        O[r1 + p]     = tf32r(oacc[j][2] * inv1);
        O[r1 + p + 8] = tf32r(oacc[j][3] * inv1);
    }
}

// ---------------- host orchestration ----------------
static void launch_gemm(const float* A, const float* B, const float* bias,
                        float* C, float* Cp, int M, int N, int K, int mode,
                        const float* res, const float* sst, const float* temb,
                        int gidx, int rpb)
{
    dim3 grid(M / 128, N / 128);
    gemm_tf32<<<grid, 128, GEMM_SMEM>>>(A, B, bias, C, Cp, N, K, mode,
                                        res, sst, temb, gidx, rpb);
}

extern "C" void kernel_launch(void* const* d_in, const int* in_sizes, int n_in,
                              void* d_out, int out_size)
{
    const float* hs    = (const float*)d_in[0];
    const float* enc   = (const float*)d_in[1];
    const float* temb  = (const float*)d_in[2];
    const float* cosT  = (const float*)d_in[3];
    const float* sinT  = (const float*)d_in[4];
    const float* sst   = (const float*)d_in[5];
    const float* w_qkv = (const float*)d_in[6];
    const float* b_qkv = (const float*)d_in[7];
    const float* rms_q1= (const float*)d_in[8];
    const float* rms_k1= (const float*)d_in[9];
    const float* w_o1  = (const float*)d_in[10];
    const float* b_o1  = (const float*)d_in[11];
    const float* ln2_g = (const float*)d_in[12];
    const float* ln2_b = (const float*)d_in[13];
    const float* w_q2  = (const float*)d_in[14];
    const float* b_q2  = (const float*)d_in[15];
    const float* w_kv2 = (const float*)d_in[16];
    const float* b_kv2 = (const float*)d_in[17];
    const float* rms_q2= (const float*)d_in[18];
    const float* rms_k2= (const float*)d_in[19];
    const float* w_o2  = (const float*)d_in[20];
    const float* b_o2  = (const float*)d_in[21];
    const float* w_ff1 = (const float*)d_in[22];
    const float* b_ff1 = (const float*)d_in[23];
    const float* w_ff2 = (const float*)d_in[24];
    const float* b_ff2 = (const float*)d_in[25];
    float* out = (float*)d_out;

    float *pqkv, *pq, *ph, *pkv, *px, *pao, *pf, *penc;
    float *wt0, *wt1, *wt2, *wt3, *wt4, *wt5, *wt6;
    bf16 *pqah, *pqal, *pkah, *pkal, *pvth, *pvtl;
    cudaGetSymbolAddress((void**)&pqkv, g_qkv);
    cudaGetSymbolAddress((void**)&pq,   g_q);
    cudaGetSymbolAddress((void**)&ph,   g_h);
    cudaGetSymbolAddress((void**)&pkv,  g_kv);
    cudaGetSymbolAddress((void**)&px,   g_x);
    cudaGetSymbolAddress((void**)&pao,  g_ao);
    cudaGetSymbolAddress((void**)&pf,   g_f);
    cudaGetSymbolAddress((void**)&penc, g_enc);
    cudaGetSymbolAddress((void**)&wt0, g_wt0);
    cudaGetSymbolAddress((void**)&wt1, g_wt1);
    cudaGetSymbolAddress((void**)&wt2, g_wt2);
    cudaGetSymbolAddress((void**)&wt3, g_wt3);
    cudaGetSymbolAddress((void**)&wt4, g_wt4);
    cudaGetSymbolAddress((void**)&wt5, g_wt5);
    cudaGetSymbolAddress((void**)&wt6, g_wt6);
    cudaGetSymbolAddress((void**)&pqah, g_qah); cudaGetSymbolAddress((void**)&pqal, g_qal);
    cudaGetSymbolAddress((void**)&pkah, g_kah); cudaGetSymbolAddress((void**)&pkal, g_kal);
    cudaGetSymbolAddress((void**)&pvth, g_vth); cudaGetSymbolAddress((void**)&pvtl, g_vtl);

    cudaFuncSetAttribute(gemm_tf32, cudaFuncAttributeMaxDynamicSharedMemorySize, GEMM_SMEM);
    cudaFuncSetAttribute(attn_mma, cudaFuncAttributeMaxDynamicSharedMemorySize, ATT_SMEM);

    const float QSCALE = (float)(0.08838834764831845 * 1.4426950408889634); // scale*log2(e)

    // weight / encoder conversion to tf32-permuted f32
    convert_kernel<<<3 * DIMC, 256>>>(w_qkv, wt0, DIMC);
    convert_kernel<<<DIMC, 256>>>(w_o1,  wt1, DIMC);
    convert_kernel<<<DIMC, 256>>>(w_q2,  wt2, DIMC);
    convert_kernel<<<2 * DIMC, 256>>>(w_kv2, wt3, DIMC);
    convert_kernel<<<DIMC, 256>>>(w_o2,  wt4, DIMC);
    convert_kernel<<<FFNN, 256>>>(w_ff1, wt5, DIMC);
    convert_kernel<<<DIMC, 256>>>(w_ff2, wt6, FFNN);
    convert_kernel<<<ROWSC, 256>>>(enc, penc, DIMC);

    // 1) x = modLN(h) -> tf32-permuted
    ln_kernel<<<ROWS, 256>>>(hs, px, nullptr, nullptr, sst, temb, 0, 1, SS);
    // 2) qkv = x @ w_qkv^T + b (f32, normal layout)
    launch_gemm(px, wt0, b_qkv, pqkv, nullptr, ROWS, 3 * DIMC, DIMC, 0,
                nullptr, nullptr, nullptr, 0, SS);
    // 3) q,k = rope(rms(.)) -> bf16 hi/lo ; V^T
    rmsrope_kernel<<<ROWS, 256>>>(pqkv, 3 * DIMC, 0,    pqah, pqal, rms_q1, cosT, sinT, SS, QSCALE);
    rmsrope_kernel<<<ROWS, 256>>>(pqkv, 3 * DIMC, DIMC, pkah, pkal, rms_k1, cosT, sinT, SS, 1.f);
    vtrans_kernel<<<dim3(SS / 32, HH, BB), 256>>>(pqkv, 3 * DIMC, 2 * DIMC, pvth, pvtl, SS);
    // 4) self-attention -> tf32-permuted
    attn_mma<<<dim3(SS / 128, HH, BB), 256, ATT_SMEM>>>(
        pqah, pqal, pkah, pkal, pvth, pvtl, pao, SS, SS);
    // 5) h = hidden + gate_sa * (attn @ w_o1^T + b_o1)
    launch_gemm(pao, wt1, b_o1, ph, nullptr, ROWS, DIMC, DIMC, 2, hs, sst, temb, 2, SS);
    // 6) x = LN(h, g, b)
    ln_kernel<<<ROWS, 256>>>(ph, px, ln2_g, ln2_b, nullptr, nullptr, 0, 0, SS);
    // 7) q2 = rms(x @ w_q2^T + b_q2)
    launch_gemm(px, wt2, b_q2, pq, nullptr, ROWS, DIMC, DIMC, 0,
                nullptr, nullptr, nullptr, 0, SS);
    rms_out_kernel<<<ROWS, 256>>>(pq, DIMC, 0, pqah, pqal, rms_q2, QSCALE);
    // 8) kv = enc @ w_kv2^T + b ; k2 = rms ; v2^T
    launch_gemm(penc, wt3, b_kv2, pkv, nullptr, ROWSC, 2 * DIMC, DIMC, 0,
                nullptr, nullptr, nullptr, 0, SCC);
    rms_out_kernel<<<ROWSC, 256>>>(pkv, 2 * DIMC, 0, pkah, pkal, rms_k2, 1.f);
    vtrans_kernel<<<dim3(SCC / 32, HH, BB), 256>>>(pkv, 2 * DIMC, DIMC, pvth, pvtl, SCC);
    // 9) cross-attention -> tf32-permuted
    attn_mma<<<dim3(SS / 128, HH, BB), 256, ATT_SMEM>>>(
        pqah, pqal, pkah, pkal, pvth, pvtl, pao, SS, SCC);
    // 10) h += attn @ w_o2^T + b_o2
    launch_gemm(pao, wt4, b_o2, ph, nullptr, ROWS, DIMC, DIMC, 1, ph, nullptr, nullptr, 0, SS);
    // 11) x = modLN(h; shift=3, scale=4)
    ln_kernel<<<ROWS, 256>>>(ph, px, nullptr, nullptr, sst, temb, 3, 4, SS);
    // 12) f = gelu(x @ w_ff1^T + b_ff1) -> tf32-permuted
    launch_gemm(px, wt5, b_ff1, nullptr, pf, ROWS, FFNN, DIMC, 3,
                nullptr, nullptr, nullptr, 0, SS);
    // 13) out = h + gate_ff * (f @ w_ff2^T + b_ff2)
    launch_gemm(pf, wt6, b_ff2, out, nullptr, ROWS, DIMC, FFNN, 2, ph, sst, temb, 5, SS);
}

// round 10
// speedup vs baseline: 1.1175x; 1.1175x over previous
#include <cuda_runtime.h>
#include <cuda_bf16.h>
#include <math.h>
#include <stdint.h>

#define DIMC 2560
#define BB 2
#define SS 2048
#define SCC 512
#define HH 20
#define HDD 128
#define FFNN 10240
#define EPSF 1e-6f
#define ROWS (BB*SS)      /* 4096 */
#define ROWSC (BB*SCC)    /* 1024 */

typedef __nv_bfloat16 bf16;
typedef __nv_bfloat162 bf162;

// ---------------- scratch (device globals) ----------------
__device__ float g_qkv[(size_t)ROWS*3*DIMC];
__device__ float g_q  [(size_t)ROWS*DIMC];
__device__ float g_h  [(size_t)ROWS*DIMC];
__device__ float g_kv [(size_t)ROWSC*2*DIMC];
__device__ float g_x  [(size_t)ROWS*DIMC];
__device__ float g_ao [(size_t)ROWS*DIMC];
__device__ float g_f  [(size_t)ROWS*FFNN];
__device__ float g_enc[(size_t)ROWSC*DIMC];
__device__ float g_wt0[(size_t)3*DIMC*DIMC];
__device__ float g_wt1[(size_t)DIMC*DIMC];
__device__ float g_wt2[(size_t)DIMC*DIMC];
__device__ float g_wt3[(size_t)2*DIMC*DIMC];
__device__ float g_wt4[(size_t)DIMC*DIMC];
__device__ float g_wt5[(size_t)FFNN*DIMC];
__device__ float g_wt6[(size_t)DIMC*FFNN];
__device__ bf16 g_qah[(size_t)ROWS*DIMC], g_qal[(size_t)ROWS*DIMC];
__device__ bf16 g_kah[(size_t)ROWS*DIMC], g_kal[(size_t)ROWS*DIMC];
__device__ bf16 g_vth[(size_t)BB*HH*HDD*SS], g_vtl[(size_t)BB*HH*HDD*SS];

// ---------------- helpers ----------------
__device__ __forceinline__ void cp_async16(uint32_t saddr, const void* gaddr){
    asm volatile("cp.async.cg.shared.global [%0], [%1], 16;" :: "r"(saddr), "l"(gaddr));
}
__device__ __forceinline__ void cp_commit(){ asm volatile("cp.async.commit_group;" ::: "memory"); }
__device__ __forceinline__ uint32_t smem_u32(const void* p){
    uint32_t a; asm("{ .reg .u64 t; cvta.to.shared.u64 t, %1; cvt.u32.u64 %0, t; }" : "=r"(a) : "l"(p)); return a;
}
__device__ __forceinline__ void mma16816(float* d, const uint32_t* a, const uint32_t* b){
    asm volatile("mma.sync.aligned.m16n8k16.row.col.f32.bf16.bf16.f32 "
        "{%0,%1,%2,%3}, {%4,%5,%6,%7}, {%8,%9}, {%0,%1,%2,%3};"
        : "+f"(d[0]), "+f"(d[1]), "+f"(d[2]), "+f"(d[3])
        : "r"(a[0]), "r"(a[1]), "r"(a[2]), "r"(a[3]), "r"(b[0]), "r"(b[1]));
}
__device__ __forceinline__ void mma_tf32(float* d, const uint32_t* a, const uint32_t* b){
    asm volatile("mma.sync.aligned.m16n8k8.row.col.f32.tf32.tf32.f32 "
        "{%0,%1,%2,%3}, {%4,%5,%6,%7}, {%8,%9}, {%0,%1,%2,%3};"
        : "+f"(d[0]), "+f"(d[1]), "+f"(d[2]), "+f"(d[3])
        : "r"(a[0]), "r"(a[1]), "r"(a[2]), "r"(a[3]), "r"(b[0]), "r"(b[1]));
}
__device__ __forceinline__ void ldmatrix_x4(uint32_t* r, uint32_t addr){
    asm volatile("ldmatrix.sync.aligned.m8n8.x4.shared.b16 {%0,%1,%2,%3}, [%4];"
        : "=r"(r[0]), "=r"(r[1]), "=r"(r[2]), "=r"(r[3]) : "r"(addr));
}
__device__ __forceinline__ void lds128(uint32_t* r, uint32_t addr){
    asm volatile("ld.shared.v4.b32 {%0,%1,%2,%3}, [%4];"
        : "=r"(r[0]), "=r"(r[1]), "=r"(r[2]), "=r"(r[3]) : "r"(addr));
}
__device__ __forceinline__ float ex2f(float x){
    float y; asm("ex2.approx.f32 %0, %1;" : "=f"(y) : "f"(x)); return y;
}
__device__ __forceinline__ uint32_t pack_bf16(float a, float b){
    bf162 t; t.x = __float2bfloat16(a); t.y = __float2bfloat16(b);
    return *(uint32_t*)&t;
}
__device__ __forceinline__ float gelu_tanh(float u){
    return 0.5f * u * (1.f + tanhf(0.7978845608028654f * (u + 0.044715f * u * u * u)));
}
__device__ __forceinline__ float tf32r(float x){
    uint32_t u; asm("cvt.rna.tf32.f32 %0, %1;" : "=r"(u) : "f"(x));
    return __uint_as_float(u);
}
__device__ __forceinline__ int permc(int c){
    return (c & ~31) | ((c & 3) << 3) | ((c & 31) >> 2);
}

// ---------------- weight/encoder convert: f32 -> tf32-rounded, K-permuted ---
__global__ __launch_bounds__(256) void convert_kernel(
    const float* __restrict__ src, float* __restrict__ dst, int K)
{
    const float* s = src + (size_t)blockIdx.x * K;
    float* d = dst + (size_t)blockIdx.x * K;
    for (int c = threadIdx.x; c < K; c += 256)
        d[permc(c)] = tf32r(s[c]);
}

// ---------------- LayerNorm -> tf32-permuted f32 ----------------
__global__ __launch_bounds__(256) void ln_kernel(
    const float* __restrict__ x, float* __restrict__ o,
    const float* __restrict__ gamma, const float* __restrict__ beta,
    const float* __restrict__ sst, const float* __restrict__ temb,
    int shift_idx, int scale_idx, int S)
{
    int row = blockIdx.x;
    int b = row / S;
    const float* xr = x + (size_t)row * DIMC;
    float vals[10];
    float s1 = 0.f, s2 = 0.f;
#pragma unroll
    for (int i = 0; i < 10; ++i) {
        float v = xr[threadIdx.x + i * 256];
        vals[i] = v; s1 += v; s2 += v * v;
    }
#pragma unroll
    for (int o2 = 16; o2 > 0; o2 >>= 1) {
        s1 += __shfl_xor_sync(0xffffffffu, s1, o2);
        s2 += __shfl_xor_sync(0xffffffffu, s2, o2);
    }
    __shared__ float red[16];
    int wid = threadIdx.x >> 5;
    if ((threadIdx.x & 31) == 0) { red[wid] = s1; red[8 + wid] = s2; }
    __syncthreads();
    float ts = 0.f, tq = 0.f;
#pragma unroll
    for (int i = 0; i < 8; ++i) { ts += red[i]; tq += red[8 + i]; }
    float mean = ts * (1.f / DIMC);
    float var  = tq * (1.f / DIMC) - mean * mean;
    float inv  = rsqrtf(var + EPSF);
    size_t ro = (size_t)row * DIMC;
#pragma unroll
    for (int i = 0; i < 10; ++i) {
        int c = threadIdx.x + i * 256;
        float y = (vals[i] - mean) * inv;
        if (sst) {
            float scv = sst[scale_idx * DIMC + c] + temb[((size_t)b * 6 + scale_idx) * DIMC + c];
            float shv = sst[shift_idx * DIMC + c] + temb[((size_t)b * 6 + shift_idx) * DIMC + c];
            y = y * (1.f + scv) + shv;
        } else if (gamma) {
            y = y * gamma[c] + beta[c];
        }
        o[ro + permc(c)] = tf32r(y);
    }
}

// ---------------- RMSNorm + RoPE -> bf16 hi/lo (scaled) --------------------
__global__ __launch_bounds__(256) void rmsrope_kernel(
    const float* __restrict__ in, int istride, int ioff,
    bf16* __restrict__ ohi, bf16* __restrict__ olo, const float* __restrict__ w,
    const float* __restrict__ cosT, const float* __restrict__ sinT, int S, float scale)
{
    int row = blockIdx.x;
    int s = row % S;
    const float* xr = in + (size_t)row * istride + ioff;
    float vals[10];
    float sq = 0.f;
#pragma unroll
    for (int i = 0; i < 10; ++i) {
        float v = xr[threadIdx.x + i * 256];
        vals[i] = v; sq += v * v;
    }
#pragma unroll
    for (int o = 16; o > 0; o >>= 1) sq += __shfl_xor_sync(0xffffffffu, sq, o);
    __shared__ float red[8];
    int wid = threadIdx.x >> 5;
    if ((threadIdx.x & 31) == 0) red[wid] = sq;
    __syncthreads();
    float tq = 0.f;
#pragma unroll
    for (int i = 0; i < 8; ++i) tq += red[i];
    float inv = rsqrtf(tq * (1.f / DIMC) + EPSF);
    size_t ro = (size_t)row * DIMC;
#pragma unroll
    for (int i = 0; i < 10; ++i) {
        int c = threadIdx.x + i * 256;
        int d = c & (HDD - 1);
        int pc = (d < 64) ? c + 64 : c - 64;
        float y  = vals[i] * inv * w[c];
        float py = xr[pc]  * inv * w[pc];
        float cv = cosT[(size_t)s * HDD + d];
        float sv = sinT[(size_t)s * HDD + d];
        float val = (y * cv + ((d < 64) ? -py : py) * sv) * scale;
        bf16 h = __float2bfloat16(val);
        ohi[ro + c] = h;
        olo[ro + c] = __float2bfloat16(val - __bfloat162float(h));
    }
}

// ---------------- RMSNorm -> bf16 hi/lo (scaled) ----------------
__global__ __launch_bounds__(256) void rms_out_kernel(
    const float* __restrict__ in, int istride, int ioff,
    bf16* __restrict__ ohi, bf16* __restrict__ olo,
    const float* __restrict__ w, float scale)
{
    int row = blockIdx.x;
    const float* xr = in + (size_t)row * istride + ioff;
    float vals[10];
    float sq = 0.f;
#pragma unroll
    for (int i = 0; i < 10; ++i) {
        float v = xr[threadIdx.x + i * 256];
        vals[i] = v; sq += v * v;
    }
#pragma unroll
    for (int o = 16; o > 0; o >>= 1) sq += __shfl_xor_sync(0xffffffffu, sq, o);
    __shared__ float red[8];
    int wid = threadIdx.x >> 5;
    if ((threadIdx.x & 31) == 0) red[wid] = sq;
    __syncthreads();
    float tq = 0.f;
#pragma unroll
    for (int i = 0; i < 8; ++i) tq += red[i];
    float inv = rsqrtf(tq * (1.f / DIMC) + EPSF);
    size_t ro = (size_t)row * DIMC;
#pragma unroll
    for (int i = 0; i < 10; ++i) {
        int c = threadIdx.x + i * 256;
        float val = vals[i] * inv * w[c] * scale;
        bf16 h = __float2bfloat16(val);
        ohi[ro + c] = h;
        olo[ro + c] = __float2bfloat16(val - __bfloat162float(h));
    }
}

// ---------------- V transpose: f32 -> bf16 hi/lo [b,h,d,s] ------------------
__global__ __launch_bounds__(256) void vtrans_kernel(
    const float* __restrict__ in, int istride, int ioff,
    bf16* __restrict__ ohi, bf16* __restrict__ olo, int Skv)
{
    __shared__ float tile[32 * 129];
    int s0 = blockIdx.x * 32;
    int h  = blockIdx.y;
    int b  = blockIdx.z;
    int tid = threadIdx.x;
#pragma unroll
    for (int i = 0; i < 16; ++i) {
        int id = i * 256 + tid;
        int s = id >> 7, d = id & 127;
        tile[s * 129 + d] = in[(size_t)(b * Skv + s0 + s) * istride + ioff + h * HDD + d];
    }
    __syncthreads();
#pragma unroll
    for (int i = 0; i < 16; ++i) {
        int id = i * 256 + tid;
        int d = id >> 5, s = id & 31;
        float v = tile[s * 129 + d];
        bf16 hh = __float2bfloat16(v);
        size_t o = ((size_t)((b * HH + h) * HDD + d)) * Skv + s0 + s;
        ohi[o] = hh;
        olo[o] = __float2bfloat16(v - __bfloat162float(hh));
    }
}

// ---------------- TF32 GEMM: 128x128 CTA, 8 warps of 32x64, 3-stage ---------
#define GPITCH 144
#define GTILEB (128 * GPITCH)            /* 18432 */
#define GSTAGEB (2 * GTILEB)             /* 36864 */
#define GEMM_SMEM (3 * GSTAGEB)          /* 110592 */

__global__ __launch_bounds__(256, 2) void gemm_tf32(
    const float* __restrict__ A, const float* __restrict__ B,
    const float* __restrict__ bias,
    float* __restrict__ C, float* __restrict__ Cp,
    int N, int K, int mode,
    const float* __restrict__ res, const float* __restrict__ sst,
    const float* __restrict__ temb, int gate_idx, int rows_per_batch)
{
    extern __shared__ char smem[];
    const uint32_t sb = smem_u32(smem);
    const int tid = threadIdx.x;
    const int wid = tid >> 5, lane = tid & 31;
    const int wm = wid & 3, wn = wid >> 2;      // 4x2 warp grid, warp = 32x64
    const int g = lane >> 2, tig = lane & 3;
    const int mt = blockIdx.x, nt = blockIdx.y;

    const int NIT = K >> 5;
    const char* Ag = (const char*)(A + (size_t)mt * 128 * K);
    const char* Bg = (const char*)(B + (size_t)nt * 128 * K);
    const size_t grb = (size_t)K * 4;

    auto load_tile = [&](int kc, int buf) {
        uint32_t s0 = sb + (uint32_t)buf * GSTAGEB;
        const char* a0 = Ag + (size_t)kc * 128;
        const char* b0 = Bg + (size_t)kc * 128;
#pragma unroll
        for (int i = 0; i < 4; ++i) {
            int idx = i * 256 + tid;
            int r = idx >> 3, c = idx & 7;
            cp_async16(s0 + (uint32_t)(r * GPITCH + c * 16), a0 + (size_t)r * grb + c * 16);
        }
#pragma unroll
        for (int i = 0; i < 4; ++i) {
            int idx = i * 256 + tid;
            int r = idx >> 3, c = idx & 7;
            cp_async16(s0 + GTILEB + (uint32_t)(r * GPITCH + c * 16), b0 + (size_t)r * grb + c * 16);
        }
        cp_commit();
    };

    load_tile(0, 0);
    if (NIT > 1) load_tile(1, 1);

    float acc[2][8][4];
#pragma unroll
    for (int mi = 0; mi < 2; ++mi)
#pragma unroll
        for (int ni = 0; ni < 8; ++ni)
#pragma unroll
            for (int j = 0; j < 4; ++j) acc[mi][ni][j] = 0.f;

    const uint32_t aL = (uint32_t)((wm * 32 + g) * GPITCH + tig * 32);
    const uint32_t bL = (uint32_t)((wn * 64 + g) * GPITCH + tig * 32);

    int buf = 0;
    for (int it = 0; it < NIT; ++it) {
        asm volatile("cp.async.wait_group 1;" ::: "memory");
        __syncthreads();
        if (it + 2 < NIT) {
            int nb = buf + 2; if (nb >= 3) nb -= 3;
            load_tile(it + 2, nb);
        }
        uint32_t su = sb + (uint32_t)buf * GSTAGEB;
        uint32_t sA = su + aL;
        uint32_t sB = su + GTILEB + bL;
        // two k16 halves; each LDS.128 carries fragments for two k8 steps
#pragma unroll
        for (int h2 = 0; h2 < 2; ++h2) {
            uint32_t off = (uint32_t)(h2 * 16);
            uint32_t am[2][8];
#pragma unroll
            for (int mi = 0; mi < 2; ++mi) {
                lds128(&am[mi][0], sA + (uint32_t)(mi * 16 * GPITCH) + off);
                lds128(&am[mi][4], sA + (uint32_t)((mi * 16 + 8) * GPITCH) + off);
            }
#pragma unroll
            for (int bg = 0; bg < 2; ++bg) {
                uint32_t bm[4][4];
#pragma unroll
                for (int nj = 0; nj < 4; ++nj)
                    lds128(&bm[nj][0], sB + (uint32_t)((bg * 4 + nj) * 8 * GPITCH) + off);
#pragma unroll
                for (int mi = 0; mi < 2; ++mi) {
                    uint32_t afL[4] = {am[mi][0], am[mi][4], am[mi][1], am[mi][5]};
                    uint32_t afH[4] = {am[mi][2], am[mi][6], am[mi][3], am[mi][7]};
#pragma unroll
                    for (int nj = 0; nj < 4; ++nj) {
                        mma_tf32(acc[mi][bg * 4 + nj], afL, &bm[nj][0]);
                        mma_tf32(acc[mi][bg * 4 + nj], afH, &bm[nj][2]);
                    }
                }
            }
        }
        ++buf; if (buf >= 3) buf = 0;
    }

    // ---- epilogue ----
#pragma unroll
    for (int mi = 0; mi < 2; ++mi) {
#pragma unroll
        for (int half = 0; half < 2; ++half) {
            int m = mt * 128 + wm * 32 + mi * 16 + g + half * 8;
            size_t rowb = (size_t)m * N;
#pragma unroll
            for (int ni = 0; ni < 8; ++ni) {
                int n = nt * 128 + wn * 64 + ni * 8 + tig * 2;
                float v0 = acc[mi][ni][half * 2 + 0] + bias[n];
                float v1 = acc[mi][ni][half * 2 + 1] + bias[n + 1];
                if (mode == 3) {
                    int p = permc(n);
                    Cp[rowb + p]     = tf32r(gelu_tanh(v0));
                    Cp[rowb + p + 8] = tf32r(gelu_tanh(v1));
                } else if (mode == 2) {
                    int bb = m / rows_per_batch;
                    float g0 = sst[(size_t)gate_idx * N + n]     + temb[((size_t)bb * 6 + gate_idx) * N + n];
                    float g1 = sst[(size_t)gate_idx * N + n + 1] + temb[((size_t)bb * 6 + gate_idx) * N + n + 1];
                    float2 rv = *(const float2*)(res + rowb + n);
                    float2 w; w.x = rv.x + g0 * v0; w.y = rv.y + g1 * v1;
                    *(float2*)(C + rowb + n) = w;
                } else if (mode == 1) {
                    float2 rv = *(const float2*)(res + rowb + n);
                    float2 w; w.x = rv.x + v0; w.y = rv.y + v1;
                    *(float2*)(C + rowb + n) = w;
                } else {
                    float2 w; w.x = v0; w.y = v1;
                    *(float2*)(C + rowb + n) = w;
                }
            }
        }
    }
}

// ---------------- mma flash attention (split-bf16, 3-term) -----------------
#define AKH 0
#define AKL 17408
#define AVH 34816
#define AVL 53248
#define ASTG 71680
#define ATT_SMEM (2 * ASTG)   /* 143360 */

__global__ __launch_bounds__(256) void attn_mma(
    const bf16* __restrict__ qh, const bf16* __restrict__ ql,
    const bf16* __restrict__ kh, const bf16* __restrict__ kl,
    const bf16* __restrict__ vth, const bf16* __restrict__ vtl,
    float* __restrict__ O,
    int S, int Skv)
{
    extern __shared__ char sm[];
    const uint32_t sb = smem_u32(sm);
    const int tid = threadIdx.x;
    const int wid = tid >> 5, lane = tid & 31;
    const int g = lane >> 2, tig = lane & 3;
    const int h = blockIdx.y, b = blockIdx.z;
    const int q0 = blockIdx.x * 128 + wid * 16;

    const bf16* qbh = qh + ((size_t)(b * S + q0 + g) * DIMC + h * HDD + tig * 2);
    const bf16* qbl = ql + ((size_t)(b * S + q0 + g) * DIMC + h * HDD + tig * 2);
    uint32_t qfh[8][4], qfl[8][4];
#pragma unroll
    for (int kc = 0; kc < 8; ++kc) {
        qfh[kc][0] = *(const uint32_t*)(qbh + kc * 16);
        qfh[kc][1] = *(const uint32_t*)(qbh + 8 * DIMC + kc * 16);
        qfh[kc][2] = *(const uint32_t*)(qbh + kc * 16 + 8);
        qfh[kc][3] = *(const uint32_t*)(qbh + 8 * DIMC + kc * 16 + 8);
        qfl[kc][0] = *(const uint32_t*)(qbl + kc * 16);
        qfl[kc][1] = *(const uint32_t*)(qbl + 8 * DIMC + kc * 16);
        qfl[kc][2] = *(const uint32_t*)(qbl + kc * 16 + 8);
        qfl[kc][3] = *(const uint32_t*)(qbl + 8 * DIMC + kc * 16 + 8);
    }

    float oacc[16][4];
#pragma unroll
    for (int j = 0; j < 16; ++j)
#pragma unroll
        for (int i = 0; i < 4; ++i) oacc[j][i] = 0.f;
    float mrow0 = -1e30f, mrow1 = -1e30f, lrow0 = 0.f, lrow1 = 0.f;

    const int nkt = Skv >> 6;

    auto stage = [&](int t) {
        uint32_t s0 = sb + (uint32_t)(t & 1) * ASTG;
        const char* kgh = (const char*)(kh + ((size_t)(b * Skv + t * 64) * DIMC + h * HDD));
        const char* kgl = (const char*)(kl + ((size_t)(b * Skv + t * 64) * DIMC + h * HDD));
#pragma unroll
        for (int i = 0; i < 4; ++i) {
            int id = i * 256 + tid;
            int r = id >> 4, c = id & 15;
            cp_async16(s0 + AKH + (uint32_t)(r * 272 + c * 16), kgh + (size_t)r * DIMC * 2 + c * 16);
        }
#pragma unroll
        for (int i = 0; i < 4; ++i) {
            int id = i * 256 + tid;
            int r = id >> 4, c = id & 15;
            cp_async16(s0 + AKL + (uint32_t)(r * 272 + c * 16), kgl + (size_t)r * DIMC * 2 + c * 16);
        }
        const char* vgh = (const char*)(vth + ((size_t)((b * HH + h) * HDD) * Skv + t * 64));
        const char* vgl = (const char*)(vtl + ((size_t)((b * HH + h) * HDD) * Skv + t * 64));
#pragma unroll
        for (int i = 0; i < 4; ++i) {
            int id = i * 256 + tid;
            int r = id >> 3, c = id & 7;
            cp_async16(s0 + AVH + (uint32_t)(r * 144 + c * 16), vgh + (size_t)r * Skv * 2 + c * 16);
        }
#pragma unroll
        for (int i = 0; i < 4; ++i) {
            int id = i * 256 + tid;
            int r = id >> 3, c = id & 7;
            cp_async16(s0 + AVL + (uint32_t)(r * 144 + c * 16), vgl + (size_t)r * Skv * 2 + c * 16);
        }
        cp_commit();
    };

    const uint32_t bk_lane = (uint32_t)(((lane & 7) + ((lane >> 4) << 3)) * 272 + (((lane >> 3) & 1) << 4));
    const uint32_t bv_lane = (uint32_t)(((lane & 7) + ((lane >> 4) << 3)) * 144 + (((lane >> 3) & 1) << 4));

    stage(0);
    asm volatile("cp.async.wait_group 0;" ::: "memory");
    __syncthreads();

    for (int t = 0; t < nkt; ++t) {
        bool more = (t + 1 < nkt);
        if (more) stage(t + 1);

        uint32_t kb = sb + (uint32_t)(t & 1) * ASTG;

        float sacc[8][4];
#pragma unroll
        for (int j = 0; j < 8; ++j)
#pragma unroll
            for (int i = 0; i < 4; ++i) sacc[j][i] = 0.f;
#pragma unroll
        for (int kc = 0; kc < 8; ++kc) {
#pragma unroll
            for (int j2 = 0; j2 < 4; ++j2) {
                uint32_t bh[4], bl[4];
                ldmatrix_x4(bh, kb + AKH + (uint32_t)(j2 * 16 * 272) + (uint32_t)(kc * 32) + bk_lane);
                ldmatrix_x4(bl, kb + AKL + (uint32_t)(j2 * 16 * 272) + (uint32_t)(kc * 32) + bk_lane);
                mma16816(sacc[2 * j2],     qfh[kc], &bh[0]);
                mma16816(sacc[2 * j2],     qfl[kc], &bh[0]);
                mma16816(sacc[2 * j2],     qfh[kc], &bl[0]);
                mma16816(sacc[2 * j2 + 1], qfh[kc], &bh[2]);
                mma16816(sacc[2 * j2 + 1], qfl[kc], &bh[2]);
                mma16816(sacc[2 * j2 + 1], qfh[kc], &bl[2]);
            }
        }

        float mx0 = -1e30f, mx1 = -1e30f;
#pragma unroll
        for (int j = 0; j < 8; ++j) {
            mx0 = fmaxf(mx0, fmaxf(sacc[j][0], sacc[j][1]));
            mx1 = fmaxf(mx1, fmaxf(sacc[j][2], sacc[j][3]));
        }
        mx0 = fmaxf(mx0, __shfl_xor_sync(0xffffffffu, mx0, 1));
        mx0 = fmaxf(mx0, __shfl_xor_sync(0xffffffffu, mx0, 2));
        mx1 = fmaxf(mx1, __shfl_xor_sync(0xffffffffu, mx1, 1));
        mx1 = fmaxf(mx1, __shfl_xor_sync(0xffffffffu, mx1, 2));
        float mn0 = fmaxf(mrow0, mx0), mn1 = fmaxf(mrow1, mx1);
        float cr0 = ex2f(mrow0 - mn0), cr1 = ex2f(mrow1 - mn1);
        mrow0 = mn0; mrow1 = mn1;
        lrow0 *= cr0; lrow1 *= cr1;
#pragma unroll
        for (int j = 0; j < 16; ++j) {
            oacc[j][0] *= cr0; oacc[j][1] *= cr0;
            oacc[j][2] *= cr1; oacc[j][3] *= cr1;
        }
        float ls0 = 0.f, ls1 = 0.f;
        uint32_t pah[4][4], pal[4][4];
#pragma unroll
        for (int j = 0; j < 8; ++j) {
            float p0 = ex2f(sacc[j][0] - mn0);
            float p1 = ex2f(sacc[j][1] - mn0);
            float p2 = ex2f(sacc[j][2] - mn1);
            float p3 = ex2f(sacc[j][3] - mn1);
            ls0 += p0 + p1; ls1 += p2 + p3;
            float h0 = __bfloat162float(__float2bfloat16(p0));
            float h1 = __bfloat162float(__float2bfloat16(p1));
            float h2 = __bfloat162float(__float2bfloat16(p2));
            float h3 = __bfloat162float(__float2bfloat16(p3));
            int kt = j >> 1, sl = (j & 1) * 2;
            pah[kt][sl + 0] = pack_bf16(h0, h1);
            pah[kt][sl + 1] = pack_bf16(h2, h3);
            pal[kt][sl + 0] = pack_bf16(p0 - h0, p1 - h1);
            pal[kt][sl + 1] = pack_bf16(p2 - h2, p3 - h3);
        }
        ls0 += __shfl_xor_sync(0xffffffffu, ls0, 1);
        ls0 += __shfl_xor_sync(0xffffffffu, ls0, 2);
        ls1 += __shfl_xor_sync(0xffffffffu, ls1, 1);
        ls1 += __shfl_xor_sync(0xffffffffu, ls1, 2);
        lrow0 += ls0; lrow1 += ls1;

#pragma unroll
        for (int kt = 0; kt < 4; ++kt) {
#pragma unroll
            for (int jd2 = 0; jd2 < 8; ++jd2) {
                uint32_t bh[4], bl[4];
                ldmatrix_x4(bh, kb + AVH + (uint32_t)(jd2 * 16 * 144) + (uint32_t)(kt * 32) + bv_lane);
                ldmatrix_x4(bl, kb + AVL + (uint32_t)(jd2 * 16 * 144) + (uint32_t)(kt * 32) + bv_lane);
                mma16816(oacc[2 * jd2],     pah[kt], &bh[0]);
                mma16816(oacc[2 * jd2],     pal[kt], &bh[0]);
                mma16816(oacc[2 * jd2],     pah[kt], &bl[0]);
                mma16816(oacc[2 * jd2 + 1], pah[kt], &bh[2]);
                mma16816(oacc[2 * jd2 + 1], pal[kt], &bh[2]);
                mma16816(oacc[2 * jd2 + 1], pah[kt], &bl[2]);
            }
        }

        if (more) { asm volatile("cp.async.wait_group 0;" ::: "memory"); }
        __syncthreads();
    }

    float inv0 = 1.f / lrow0, inv1 = 1.f / lrow1;
    size_t r0 = (size_t)(b * S + q0 + g) * DIMC;
    size_t r1 = r0 + 8 * DIMC;
    int cbase = h * HDD + tig * 2;
#pragma unroll
    for (int j = 0; j < 16; ++j) {
        int c = cbase + j * 8;
        int p = permc(c);
        O[r0 + p]     = tf32r(oacc[j][0] * inv0);
        O[r0 + p + 8] = tf32r(oacc[j][1] * inv0);
        O[r1 + p]     = tf32r(oacc[j][2] * inv1);
        O[r1 + p + 8] = tf32r(oacc[j][3] * inv1);
    }
}

// ---------------- host orchestration ----------------
static void launch_gemm(const float* A, const float* B, const float* bias,
                        float* C, float* Cp, int M, int N, int K, int mode,
                        const float* res, const float* sst, const float* temb,
                        int gidx, int rpb)
{
    dim3 grid(M / 128, N / 128);
    gemm_tf32<<<grid, 256, GEMM_SMEM>>>(A, B, bias, C, Cp, N, K, mode,
                                        res, sst, temb, gidx, rpb);
}

extern "C" void kernel_launch(void* const* d_in, const int* in_sizes, int n_in,
                              void* d_out, int out_size)
{
    const float* hs    = (const float*)d_in[0];
    const float* enc   = (const float*)d_in[1];
    const float* temb  = (const float*)d_in[2];
    const float* cosT  = (const float*)d_in[3];
    const float* sinT  = (const float*)d_in[4];
    const float* sst   = (const float*)d_in[5];
    const float* w_qkv = (const float*)d_in[6];
    const float* b_qkv = (const float*)d_in[7];
    const float* rms_q1= (const float*)d_in[8];
    const float* rms_k1= (const float*)d_in[9];
    const float* w_o1  = (const float*)d_in[10];
    const float* b_o1  = (const float*)d_in[11];
    const float* ln2_g = (const float*)d_in[12];
    const float* ln2_b = (const float*)d_in[13];
    const float* w_q2  = (const float*)d_in[14];
    const float* b_q2  = (const float*)d_in[15];
    const float* w_kv2 = (const float*)d_in[16];
    const float* b_kv2 = (const float*)d_in[17];
    const float* rms_q2= (const float*)d_in[18];
    const float* rms_k2= (const float*)d_in[19];
    const float* w_o2  = (const float*)d_in[20];
    const float* b_o2  = (const float*)d_in[21];
    const float* w_ff1 = (const float*)d_in[22];
    const float* b_ff1 = (const float*)d_in[23];
    const float* w_ff2 = (const float*)d_in[24];
    const float* b_ff2 = (const float*)d_in[25];
    float* out = (float*)d_out;

    float *pqkv, *pq, *ph, *pkv, *px, *pao, *pf, *penc;
    float *wt0, *wt1, *wt2, *wt3, *wt4, *wt5, *wt6;
    bf16 *pqah, *pqal, *pkah, *pkal, *pvth, *pvtl;
    cudaGetSymbolAddress((void**)&pqkv, g_qkv);
    cudaGetSymbolAddress((void**)&pq,   g_q);
    cudaGetSymbolAddress((void**)&ph,   g_h);
    cudaGetSymbolAddress((void**)&pkv,  g_kv);
    cudaGetSymbolAddress((void**)&px,   g_x);
    cudaGetSymbolAddress((void**)&pao,  g_ao);
    cudaGetSymbolAddress((void**)&pf,   g_f);
    cudaGetSymbolAddress((void**)&penc, g_enc);
    cudaGetSymbolAddress((void**)&wt0, g_wt0);
    cudaGetSymbolAddress((void**)&wt1, g_wt1);
    cudaGetSymbolAddress((void**)&wt2, g_wt2);
    cudaGetSymbolAddress((void**)&wt3, g_wt3);
    cudaGetSymbolAddress((void**)&wt4, g_wt4);
    cudaGetSymbolAddress((void**)&wt5, g_wt5);
    cudaGetSymbolAddress((void**)&wt6, g_wt6);
    cudaGetSymbolAddress((void**)&pqah, g_qah); cudaGetSymbolAddress((void**)&pqal, g_qal);
    cudaGetSymbolAddress((void**)&pkah, g_kah); cudaGetSymbolAddress((void**)&pkal, g_kal);
    cudaGetSymbolAddress((void**)&pvth, g_vth); cudaGetSymbolAddress((void**)&pvtl, g_vtl);

    cudaFuncSetAttribute(gemm_tf32, cudaFuncAttributeMaxDynamicSharedMemorySize, GEMM_SMEM);
    cudaFuncSetAttribute(attn_mma, cudaFuncAttributeMaxDynamicSharedMemorySize, ATT_SMEM);

    const float QSCALE = (float)(0.08838834764831845 * 1.4426950408889634); // scale*log2(e)

    convert_kernel<<<3 * DIMC, 256>>>(w_qkv, wt0, DIMC);
    convert_kernel<<<DIMC, 256>>>(w_o1,  wt1, DIMC);
    convert_kernel<<<DIMC, 256>>>(w_q2,  wt2, DIMC);
    convert_kernel<<<2 * DIMC, 256>>>(w_kv2, wt3, DIMC);
    convert_kernel<<<DIMC, 256>>>(w_o2,  wt4, DIMC);
    convert_kernel<<<FFNN, 256>>>(w_ff1, wt5, DIMC);
    convert_kernel<<<DIMC, 256>>>(w_ff2, wt6, FFNN);
    convert_kernel<<<ROWSC, 256>>>(enc, penc, DIMC);

    // 1) x = modLN(h) -> tf32-permuted
    ln_kernel<<<ROWS, 256>>>(hs, px, nullptr, nullptr, sst, temb, 0, 1, SS);
    // 2) qkv = x @ w_qkv^T + b (f32)
    launch_gemm(px, wt0, b_qkv, pqkv, nullptr, ROWS, 3 * DIMC, DIMC, 0,
                nullptr, nullptr, nullptr, 0, SS);
    // 3) q,k = rope(rms(.)) -> bf16 hi/lo ; V^T
    rmsrope_kernel<<<ROWS, 256>>>(pqkv, 3 * DIMC, 0,    pqah, pqal, rms_q1, cosT, sinT, SS, QSCALE);
    rmsrope_kernel<<<ROWS, 256>>>(pqkv, 3 * DIMC, DIMC, pkah, pkal, rms_k1, cosT, sinT, SS, 1.f);
    vtrans_kernel<<<dim3(SS / 32, HH, BB), 256>>>(pqkv, 3 * DIMC, 2 * DIMC, pvth, pvtl, SS);
    // 4) self-attention -> tf32-permuted
    attn_mma<<<dim3(SS / 128, HH, BB), 256, ATT_SMEM>>>(
        pqah, pqal, pkah, pkal, pvth, pvtl, pao, SS, SS);
    // 5) h = hidden + gate_sa * (attn @ w_o1^T + b_o1)
    launch_gemm(pao, wt1, b_o1, ph, nullptr, ROWS, DIMC, DIMC, 2, hs, sst, temb, 2, SS);
    // 6) x = LN(h, g, b)
    ln_kernel<<<ROWS, 256>>>(ph, px, ln2_g, ln2_b, nullptr, nullptr, 0, 0, SS);
    // 7) q2 = rms(x @ w_q2^T + b_q2)
    launch_gemm(px, wt2, b_q2, pq, nullptr, ROWS, DIMC, DIMC, 0,
                nullptr, nullptr, nullptr, 0, SS);
    rms_out_kernel<<<ROWS, 256>>>(pq, DIMC, 0, pqah, pqal, rms_q2, QSCALE);
    // 8) kv = enc @ w_kv2^T + b ; k2 = rms ; v2^T
    launch_gemm(penc, wt3, b_kv2, pkv, nullptr, ROWSC, 2 * DIMC, DIMC, 0,
                nullptr, nullptr, nullptr, 0, SCC);
    rms_out_kernel<<<ROWSC, 256>>>(pkv, 2 * DIMC, 0, pkah, pkal, rms_k2, 1.f);
    vtrans_kernel<<<dim3(SCC / 32, HH, BB), 256>>>(pkv, 2 * DIMC, DIMC, pvth, pvtl, SCC);
    // 9) cross-attention -> tf32-permuted
    attn_mma<<<dim3(SS / 128, HH, BB), 256, ATT_SMEM>>>(
        pqah, pqal, pkah, pkal, pvth, pvtl, pao, SS, SCC);
    // 10) h += attn @ w_o2^T + b_o2
    launch_gemm(pao, wt4, b_o2, ph, nullptr, ROWS, DIMC, DIMC, 1, ph, nullptr, nullptr, 0, SS);
    // 11) x = modLN(h; shift=3, scale=4)
    ln_kernel<<<ROWS, 256>>>(ph, px, nullptr, nullptr, sst, temb, 3, 4, SS);
    // 12) f = gelu(x @ w_ff1^T + b_ff1) -> tf32-permuted
    launch_gemm(px, wt5, b_ff1, nullptr, pf, ROWS, FFNN, DIMC, 3,
                nullptr, nullptr, nullptr, 0, SS);
    // 13) out = h + gate_ff * (f @ w_ff2^T + b_ff2)
    launch_gemm(pf, wt6, b_ff2, out, nullptr, ROWS, DIMC, FFNN, 2, ph, sst, temb, 5, SS);
}

// round 11
// speedup vs baseline: 2.2502x; 2.0136x over previous
#include <cuda_runtime.h>
#include <cuda_bf16.h>
#include <cuda_fp16.h>
#include <math.h>
#include <stdint.h>

#define DIMC 2560
#define BB 2
#define SS 2048
#define SCC 512
#define HH 20
#define HDD 128
#define FFNN 10240
#define EPSF 1e-6f
#define ROWS (BB*SS)      /* 4096 */
#define ROWSC (BB*SCC)    /* 1024 */

typedef __nv_bfloat16 bf16;
typedef __nv_bfloat162 bf162;

// ---------------- scratch (device globals) ----------------
__device__ float g_qkv[(size_t)ROWS*3*DIMC];
__device__ float g_q  [(size_t)ROWS*DIMC];
__device__ float g_h  [(size_t)ROWS*DIMC];
__device__ float g_kv [(size_t)ROWSC*2*DIMC];
__device__ __half g_x  [(size_t)ROWS*DIMC];     // fp16-permuted LN output
__device__ __half g_ao [(size_t)ROWS*DIMC];     // fp16-permuted attention output
__device__ __half g_f  [(size_t)ROWS*FFNN];     // fp16-permuted gelu output
__device__ __half g_enc[(size_t)ROWSC*DIMC];
__device__ __half g_wt0[(size_t)3*DIMC*DIMC];
__device__ __half g_wt1[(size_t)DIMC*DIMC];
__device__ __half g_wt2[(size_t)DIMC*DIMC];
__device__ __half g_wt3[(size_t)2*DIMC*DIMC];
__device__ __half g_wt4[(size_t)DIMC*DIMC];
__device__ __half g_wt5[(size_t)FFNN*DIMC];
__device__ __half g_wt6[(size_t)DIMC*FFNN];
__device__ bf16 g_qah[(size_t)ROWS*DIMC], g_qal[(size_t)ROWS*DIMC];
__device__ bf16 g_kah[(size_t)ROWS*DIMC], g_kal[(size_t)ROWS*DIMC];
__device__ bf16 g_vth[(size_t)BB*HH*HDD*SS], g_vtl[(size_t)BB*HH*HDD*SS];

// ---------------- helpers ----------------
__device__ __forceinline__ void cp_async16(uint32_t saddr, const void* gaddr){
    asm volatile("cp.async.cg.shared.global [%0], [%1], 16;" :: "r"(saddr), "l"(gaddr));
}
__device__ __forceinline__ void cp_commit(){ asm volatile("cp.async.commit_group;" ::: "memory"); }
__device__ __forceinline__ uint32_t smem_u32(const void* p){
    uint32_t a; asm("{ .reg .u64 t; cvta.to.shared.u64 t, %1; cvt.u32.u64 %0, t; }" : "=r"(a) : "l"(p)); return a;
}
__device__ __forceinline__ void mma16816(float* d, const uint32_t* a, const uint32_t* b){
    asm volatile("mma.sync.aligned.m16n8k16.row.col.f32.bf16.bf16.f32 "
        "{%0,%1,%2,%3}, {%4,%5,%6,%7}, {%8,%9}, {%0,%1,%2,%3};"
        : "+f"(d[0]), "+f"(d[1]), "+f"(d[2]), "+f"(d[3])
        : "r"(a[0]), "r"(a[1]), "r"(a[2]), "r"(a[3]), "r"(b[0]), "r"(b[1]));
}
__device__ __forceinline__ void mma_f16(float* d, const uint32_t* a, const uint32_t* b){
    asm volatile("mma.sync.aligned.m16n8k16.row.col.f32.f16.f16.f32 "
        "{%0,%1,%2,%3}, {%4,%5,%6,%7}, {%8,%9}, {%0,%1,%2,%3};"
        : "+f"(d[0]), "+f"(d[1]), "+f"(d[2]), "+f"(d[3])
        : "r"(a[0]), "r"(a[1]), "r"(a[2]), "r"(a[3]), "r"(b[0]), "r"(b[1]));
}
__device__ __forceinline__ void ldmatrix_x4(uint32_t* r, uint32_t addr){
    asm volatile("ldmatrix.sync.aligned.m8n8.x4.shared.b16 {%0,%1,%2,%3}, [%4];"
        : "=r"(r[0]), "=r"(r[1]), "=r"(r[2]), "=r"(r[3]) : "r"(addr));
}
__device__ __forceinline__ void lds128(uint32_t* r, uint32_t addr){
    asm volatile("ld.shared.v4.b32 {%0,%1,%2,%3}, [%4];"
        : "=r"(r[0]), "=r"(r[1]), "=r"(r[2]), "=r"(r[3]) : "r"(addr));
}
__device__ __forceinline__ float ex2f(float x){
    float y; asm("ex2.approx.f32 %0, %1;" : "=f"(y) : "f"(x)); return y;
}
__device__ __forceinline__ uint32_t pack_bf16(float a, float b){
    bf162 t; t.x = __float2bfloat16(a); t.y = __float2bfloat16(b);
    return *(uint32_t*)&t;
}
__device__ __forceinline__ float gelu_tanh(float u){
    return 0.5f * u * (1.f + tanhf(0.7978845608028654f * (u + 0.044715f * u * u * u)));
}
// fp16 K-permutation within each 32-element block: thread t (=quad lane) gets
// halves {2t,2t+1,2t+8,2t+9,2t+16,2t+17,2t+24,2t+25} as one contiguous 16B run.
__device__ __forceinline__ int permch(int c){
    int t = (c & 7) >> 1;
    int idx = (c & 1) | (((c >> 3) & 1) << 1) | (((c >> 4) & 1) << 2);
    return (c & ~31) | (t << 3) | idx;
}

// ---------------- weight/encoder convert: f32 -> fp16, K-permuted ----------
__global__ __launch_bounds__(256) void convert_kernel(
    const float* __restrict__ src, __half* __restrict__ dst, int K)
{
    const float* s = src + (size_t)blockIdx.x * K;
    __half* d = dst + (size_t)blockIdx.x * K;
    for (int c = threadIdx.x; c < K; c += 256)
        d[permch(c)] = __float2half(s[c]);
}

// ---------------- LayerNorm -> fp16-permuted ----------------
__global__ __launch_bounds__(256) void ln_kernel(
    const float* __restrict__ x, __half* __restrict__ o,
    const float* __restrict__ gamma, const float* __restrict__ beta,
    const float* __restrict__ sst, const float* __restrict__ temb,
    int shift_idx, int scale_idx, int S)
{
    int row = blockIdx.x;
    int b = row / S;
    const float* xr = x + (size_t)row * DIMC;
    float vals[10];
    float s1 = 0.f, s2 = 0.f;
#pragma unroll
    for (int i = 0; i < 10; ++i) {
        float v = xr[threadIdx.x + i * 256];
        vals[i] = v; s1 += v; s2 += v * v;
    }
#pragma unroll
    for (int o2 = 16; o2 > 0; o2 >>= 1) {
        s1 += __shfl_xor_sync(0xffffffffu, s1, o2);
        s2 += __shfl_xor_sync(0xffffffffu, s2, o2);
    }
    __shared__ float red[16];
    int wid = threadIdx.x >> 5;
    if ((threadIdx.x & 31) == 0) { red[wid] = s1; red[8 + wid] = s2; }
    __syncthreads();
    float ts = 0.f, tq = 0.f;
#pragma unroll
    for (int i = 0; i < 8; ++i) { ts += red[i]; tq += red[8 + i]; }
    float mean = ts * (1.f / DIMC);
    float var  = tq * (1.f / DIMC) - mean * mean;
    float inv  = rsqrtf(var + EPSF);
    size_t ro = (size_t)row * DIMC;
#pragma unroll
    for (int i = 0; i < 10; ++i) {
        int c = threadIdx.x + i * 256;
        float y = (vals[i] - mean) * inv;
        if (sst) {
            float scv = sst[scale_idx * DIMC + c] + temb[((size_t)b * 6 + scale_idx) * DIMC + c];
            float shv = sst[shift_idx * DIMC + c] + temb[((size_t)b * 6 + shift_idx) * DIMC + c];
            y = y * (1.f + scv) + shv;
        } else if (gamma) {
            y = y * gamma[c] + beta[c];
        }
        o[ro + permch(c)] = __float2half(y);
    }
}

// ---------------- RMSNorm + RoPE -> bf16 hi/lo (scaled) --------------------
__global__ __launch_bounds__(256) void rmsrope_kernel(
    const float* __restrict__ in, int istride, int ioff,
    bf16* __restrict__ ohi, bf16* __restrict__ olo, const float* __restrict__ w,
    const float* __restrict__ cosT, const float* __restrict__ sinT, int S, float scale)
{
    int row = blockIdx.x;
    int s = row % S;
    const float* xr = in + (size_t)row * istride + ioff;
    float vals[10];
    float sq = 0.f;
#pragma unroll
    for (int i = 0; i < 10; ++i) {
        float v = xr[threadIdx.x + i * 256];
        vals[i] = v; sq += v * v;
    }
#pragma unroll
    for (int o = 16; o > 0; o >>= 1) sq += __shfl_xor_sync(0xffffffffu, sq, o);
    __shared__ float red[8];
    int wid = threadIdx.x >> 5;
    if ((threadIdx.x & 31) == 0) red[wid] = sq;
    __syncthreads();
    float tq = 0.f;
#pragma unroll
    for (int i = 0; i < 8; ++i) tq += red[i];
    float inv = rsqrtf(tq * (1.f / DIMC) + EPSF);
    size_t ro = (size_t)row * DIMC;
#pragma unroll
    for (int i = 0; i < 10; ++i) {
        int c = threadIdx.x + i * 256;
        int d = c & (HDD - 1);
        int pc = (d < 64) ? c + 64 : c - 64;
        float y  = vals[i] * inv * w[c];
        float py = xr[pc]  * inv * w[pc];
        float cv = cosT[(size_t)s * HDD + d];
        float sv = sinT[(size_t)s * HDD + d];
        float val = (y * cv + ((d < 64) ? -py : py) * sv) * scale;
        bf16 h = __float2bfloat16(val);
        ohi[ro + c] = h;
        olo[ro + c] = __float2bfloat16(val - __bfloat162float(h));
    }
}

// ---------------- RMSNorm -> bf16 hi/lo (scaled) ----------------
__global__ __launch_bounds__(256) void rms_out_kernel(
    const float* __restrict__ in, int istride, int ioff,
    bf16* __restrict__ ohi, bf16* __restrict__ olo,
    const float* __restrict__ w, float scale)
{
    int row = blockIdx.x;
    const float* xr = in + (size_t)row * istride + ioff;
    float vals[10];
    float sq = 0.f;
#pragma unroll
    for (int i = 0; i < 10; ++i) {
        float v = xr[threadIdx.x + i * 256];
        vals[i] = v; sq += v * v;
    }
#pragma unroll
    for (int o = 16; o > 0; o >>= 1) sq += __shfl_xor_sync(0xffffffffu, sq, o);
    __shared__ float red[8];
    int wid = threadIdx.x >> 5;
    if ((threadIdx.x & 31) == 0) red[wid] = sq;
    __syncthreads();
    float tq = 0.f;
#pragma unroll
    for (int i = 0; i < 8; ++i) tq += red[i];
    float inv = rsqrtf(tq * (1.f / DIMC) + EPSF);
    size_t ro = (size_t)row * DIMC;
#pragma unroll
    for (int i = 0; i < 10; ++i) {
        int c = threadIdx.x + i * 256;
        float val = vals[i] * inv * w[c] * scale;
        bf16 h = __float2bfloat16(val);
        ohi[ro + c] = h;
        olo[ro + c] = __float2bfloat16(val - __bfloat162float(h));
    }
}

// ---------------- V transpose: f32 -> bf16 hi/lo [b,h,d,s] ------------------
__global__ __launch_bounds__(256) void vtrans_kernel(
    const float* __restrict__ in, int istride, int ioff,
    bf16* __restrict__ ohi, bf16* __restrict__ olo, int Skv)
{
    __shared__ float tile[32 * 129];
    int s0 = blockIdx.x * 32;
    int h  = blockIdx.y;
    int b  = blockIdx.z;
    int tid = threadIdx.x;
#pragma unroll
    for (int i = 0; i < 16; ++i) {
        int id = i * 256 + tid;
        int s = id >> 7, d = id & 127;
        tile[s * 129 + d] = in[(size_t)(b * Skv + s0 + s) * istride + ioff + h * HDD + d];
    }
    __syncthreads();
#pragma unroll
    for (int i = 0; i < 16; ++i) {
        int id = i * 256 + tid;
        int d = id >> 5, s = id & 31;
        float v = tile[s * 129 + d];
        bf16 hh = __float2bfloat16(v);
        size_t o = ((size_t)((b * HH + h) * HDD + d)) * Skv + s0 + s;
        ohi[o] = hh;
        olo[o] = __float2bfloat16(v - __bfloat162float(hh));
    }
}

// ---------------- FP16 GEMM: 128x128 CTA, 4 warps of 64x64, 3-stage ---------
// Operands fp16, K-permuted; smem rows 64B, XOR-swizzled 16B chunks.
#define GTILEB (128 * 64)                /* 8192 */
#define GSTAGEB (2 * GTILEB)             /* 16384 */
#define GEMM_SMEM (3 * GSTAGEB)          /* 49152 */

__global__ __launch_bounds__(128, 2) void gemm_f16(
    const __half* __restrict__ A, const __half* __restrict__ B,
    const float* __restrict__ bias,
    float* __restrict__ C, __half* __restrict__ Cp,
    int N, int K, int mode,
    const float* __restrict__ res, const float* __restrict__ sst,
    const float* __restrict__ temb, int gate_idx, int rows_per_batch)
{
    extern __shared__ char smem[];
    const uint32_t sb = smem_u32(smem);
    const int tid = threadIdx.x;
    const int wid = tid >> 5, lane = tid & 31;
    const int wm = wid & 1, wn = wid >> 1;      // 2x2 warp grid, warp = 64x64
    const int g = lane >> 2, tig = lane & 3;
    const int mt = blockIdx.x, nt = blockIdx.y;

    const int NIT = K >> 5;
    const char* Ag = (const char*)(A + (size_t)mt * 128 * K);
    const char* Bg = (const char*)(B + (size_t)nt * 128 * K);
    const size_t grb = (size_t)K * 2;

    auto load_tile = [&](int kc, int buf) {
        uint32_t s0 = sb + (uint32_t)buf * GSTAGEB;
        const char* a0 = Ag + (size_t)kc * 64;
        const char* b0 = Bg + (size_t)kc * 64;
#pragma unroll
        for (int i = 0; i < 4; ++i) {
            int idx = i * 128 + tid;
            int r = idx >> 2, c = idx & 3;
            uint32_t sw = (uint32_t)(r * 64 + ((c ^ (r & 3)) << 4));
            cp_async16(s0 + sw, a0 + (size_t)r * grb + c * 16);
        }
#pragma unroll
        for (int i = 0; i < 4; ++i) {
            int idx = i * 128 + tid;
            int r = idx >> 2, c = idx & 3;
            uint32_t sw = (uint32_t)(r * 64 + ((c ^ (r & 3)) << 4));
            cp_async16(s0 + GTILEB + sw, b0 + (size_t)r * grb + c * 16);
        }
        cp_commit();
    };

    load_tile(0, 0);
    if (NIT > 1) load_tile(1, 1);

    float acc[4][8][4];
#pragma unroll
    for (int mi = 0; mi < 4; ++mi)
#pragma unroll
        for (int ni = 0; ni < 8; ++ni)
#pragma unroll
            for (int j = 0; j < 4; ++j) acc[mi][ni][j] = 0.f;

    const uint32_t swz = (uint32_t)((tig ^ (g & 3)) << 4);

    int buf = 0;
    for (int it = 0; it < NIT; ++it) {
        asm volatile("cp.async.wait_group 1;" ::: "memory");
        __syncthreads();
        if (it + 2 < NIT) {
            int nb = buf + 2; if (nb >= 3) nb -= 3;
            load_tile(it + 2, nb);
        }
        uint32_t su = sb + (uint32_t)buf * GSTAGEB;
        // A fragments: per mi, rows R and R+8 -> 8 regs covering both k16 steps
        uint32_t am[4][8];
#pragma unroll
        for (int mi = 0; mi < 4; ++mi) {
            int R = wm * 64 + mi * 16 + g;
            lds128(&am[mi][0], su + (uint32_t)(R * 64) + swz);
            lds128(&am[mi][4], su + (uint32_t)((R + 8) * 64) + swz);
        }
        uint32_t bm[8][4];
#pragma unroll
        for (int nj = 0; nj < 8; ++nj) {
            int Rn = wn * 64 + nj * 8 + g;
            lds128(&bm[nj][0], su + GTILEB + (uint32_t)(Rn * 64) + swz);
        }
#pragma unroll
        for (int mi = 0; mi < 4; ++mi) {
            uint32_t a0[4] = {am[mi][0], am[mi][4], am[mi][1], am[mi][5]};  // k16 step 0
            uint32_t a1[4] = {am[mi][2], am[mi][6], am[mi][3], am[mi][7]};  // k16 step 1
#pragma unroll
            for (int nj = 0; nj < 8; ++nj) {
                mma_f16(acc[mi][nj], a0, &bm[nj][0]);
                mma_f16(acc[mi][nj], a1, &bm[nj][2]);
            }
        }
        ++buf; if (buf >= 3) buf = 0;
    }

    // ---- epilogue ----
#pragma unroll
    for (int mi = 0; mi < 4; ++mi) {
#pragma unroll
        for (int half = 0; half < 2; ++half) {
            int m = mt * 128 + wm * 64 + mi * 16 + g + half * 8;
            size_t rowb = (size_t)m * N;
#pragma unroll
            for (int ni = 0; ni < 8; ++ni) {
                int n = nt * 128 + wn * 64 + ni * 8 + tig * 2;
                float v0 = acc[mi][ni][half * 2 + 0] + bias[n];
                float v1 = acc[mi][ni][half * 2 + 1] + bias[n + 1];
                if (mode == 3) {
                    int p = permch(n);
                    __half2 hv; hv.x = __float2half(gelu_tanh(v0)); hv.y = __float2half(gelu_tanh(v1));
                    *(__half2*)(Cp + rowb + p) = hv;
                } else if (mode == 2) {
                    int bb = m / rows_per_batch;
                    float g0 = sst[(size_t)gate_idx * N + n]     + temb[((size_t)bb * 6 + gate_idx) * N + n];
                    float g1 = sst[(size_t)gate_idx * N + n + 1] + temb[((size_t)bb * 6 + gate_idx) * N + n + 1];
                    float2 rv = *(const float2*)(res + rowb + n);
                    float2 w; w.x = rv.x + g0 * v0; w.y = rv.y + g1 * v1;
                    *(float2*)(C + rowb + n) = w;
                } else if (mode == 1) {
                    float2 rv = *(const float2*)(res + rowb + n);
                    float2 w; w.x = rv.x + v0; w.y = rv.y + v1;
                    *(float2*)(C + rowb + n) = w;
                } else {
                    float2 w; w.x = v0; w.y = v1;
                    *(float2*)(C + rowb + n) = w;
                }
            }
        }
    }
}

// ---------------- mma flash attention (split-bf16, 3-term) -----------------
// Output: fp16, K-permuted (feeds the o-projection GEMMs).
#define AKH 0
#define AKL 17408
#define AVH 34816
#define AVL 53248
#define ASTG 71680
#define ATT_SMEM (2 * ASTG)   /* 143360 */

__global__ __launch_bounds__(256) void attn_mma(
    const bf16* __restrict__ qh, const bf16* __restrict__ ql,
    const bf16* __restrict__ kh, const bf16* __restrict__ kl,
    const bf16* __restrict__ vth, const bf16* __restrict__ vtl,
    __half* __restrict__ O,
    int S, int Skv)
{
    extern __shared__ char sm[];
    const uint32_t sb = smem_u32(sm);
    const int tid = threadIdx.x;
    const int wid = tid >> 5, lane = tid & 31;
    const int g = lane >> 2, tig = lane & 3;
    const int h = blockIdx.y, b = blockIdx.z;
    const int q0 = blockIdx.x * 128 + wid * 16;

    const bf16* qbh = qh + ((size_t)(b * S + q0 + g) * DIMC + h * HDD + tig * 2);
    const bf16* qbl = ql + ((size_t)(b * S + q0 + g) * DIMC + h * HDD + tig * 2);
    uint32_t qfh[8][4], qfl[8][4];
#pragma unroll
    for (int kc = 0; kc < 8; ++kc) {
        qfh[kc][0] = *(const uint32_t*)(qbh + kc * 16);
        qfh[kc][1] = *(const uint32_t*)(qbh + 8 * DIMC + kc * 16);
        qfh[kc][2] = *(const uint32_t*)(qbh + kc * 16 + 8);
        qfh[kc][3] = *(const uint32_t*)(qbh + 8 * DIMC + kc * 16 + 8);
        qfl[kc][0] = *(const uint32_t*)(qbl + kc * 16);
        qfl[kc][1] = *(const uint32_t*)(qbl + 8 * DIMC + kc * 16);
        qfl[kc][2] = *(const uint32_t*)(qbl + kc * 16 + 8);
        qfl[kc][3] = *(const uint32_t*)(qbl + 8 * DIMC + kc * 16 + 8);
    }

    float oacc[16][4];
#pragma unroll
    for (int j = 0; j < 16; ++j)
#pragma unroll
        for (int i = 0; i < 4; ++i) oacc[j][i] = 0.f;
    float mrow0 = -1e30f, mrow1 = -1e30f, lrow0 = 0.f, lrow1 = 0.f;

    const int nkt = Skv >> 6;

    auto stage = [&](int t) {
        uint32_t s0 = sb + (uint32_t)(t & 1) * ASTG;
        const char* kgh = (const char*)(kh + ((size_t)(b * Skv + t * 64) * DIMC + h * HDD));
        const char* kgl = (const char*)(kl + ((size_t)(b * Skv + t * 64) * DIMC + h * HDD));
#pragma unroll
        for (int i = 0; i < 4; ++i) {
            int id = i * 256 + tid;
            int r = id >> 4, c = id & 15;
            cp_async16(s0 + AKH + (uint32_t)(r * 272 + c * 16), kgh + (size_t)r * DIMC * 2 + c * 16);
        }
#pragma unroll
        for (int i = 0; i < 4; ++i) {
            int id = i * 256 + tid;
            int r = id >> 4, c = id & 15;
            cp_async16(s0 + AKL + (uint32_t)(r * 272 + c * 16), kgl + (size_t)r * DIMC * 2 + c * 16);
        }
        const char* vgh = (const char*)(vth + ((size_t)((b * HH + h) * HDD) * Skv + t * 64));
        const char* vgl = (const char*)(vtl + ((size_t)((b * HH + h) * HDD) * Skv + t * 64));
#pragma unroll
        for (int i = 0; i < 4; ++i) {
            int id = i * 256 + tid;
            int r = id >> 3, c = id & 7;
            cp_async16(s0 + AVH + (uint32_t)(r * 144 + c * 16), vgh + (size_t)r * Skv * 2 + c * 16);
        }
#pragma unroll
        for (int i = 0; i < 4; ++i) {
            int id = i * 256 + tid;
            int r = id >> 3, c = id & 7;
            cp_async16(s0 + AVL + (uint32_t)(r * 144 + c * 16), vgl + (size_t)r * Skv * 2 + c * 16);
        }
        cp_commit();
    };

    const uint32_t bk_lane = (uint32_t)(((lane & 7) + ((lane >> 4) << 3)) * 272 + (((lane >> 3) & 1) << 4));
    const uint32_t bv_lane = (uint32_t)(((lane & 7) + ((lane >> 4) << 3)) * 144 + (((lane >> 3) & 1) << 4));

    stage(0);
    asm volatile("cp.async.wait_group 0;" ::: "memory");
    __syncthreads();

    for (int t = 0; t < nkt; ++t) {
        bool more = (t + 1 < nkt);
        if (more) stage(t + 1);

        uint32_t kb = sb + (uint32_t)(t & 1) * ASTG;

        float sacc[8][4];
#pragma unroll
        for (int j = 0; j < 8; ++j)
#pragma unroll
            for (int i = 0; i < 4; ++i) sacc[j][i] = 0.f;
#pragma unroll
        for (int kc = 0; kc < 8; ++kc) {
#pragma unroll
            for (int j2 = 0; j2 < 4; ++j2) {
                uint32_t bh[4], bl[4];
                ldmatrix_x4(bh, kb + AKH + (uint32_t)(j2 * 16 * 272) + (uint32_t)(kc * 32) + bk_lane);
                ldmatrix_x4(bl, kb + AKL + (uint32_t)(j2 * 16 * 272) + (uint32_t)(kc * 32) + bk_lane);
                mma16816(sacc[2 * j2],     qfh[kc], &bh[0]);
                mma16816(sacc[2 * j2],     qfl[kc], &bh[0]);
                mma16816(sacc[2 * j2],     qfh[kc], &bl[0]);
                mma16816(sacc[2 * j2 + 1], qfh[kc], &bh[2]);
                mma16816(sacc[2 * j2 + 1], qfl[kc], &bh[2]);
                mma16816(sacc[2 * j2 + 1], qfh[kc], &bl[2]);
            }
        }

        float mx0 = -1e30f, mx1 = -1e30f;
#pragma unroll
        for (int j = 0; j < 8; ++j) {
            mx0 = fmaxf(mx0, fmaxf(sacc[j][0], sacc[j][1]));
            mx1 = fmaxf(mx1, fmaxf(sacc[j][2], sacc[j][3]));
        }
        mx0 = fmaxf(mx0, __shfl_xor_sync(0xffffffffu, mx0, 1));
        mx0 = fmaxf(mx0, __shfl_xor_sync(0xffffffffu, mx0, 2));
        mx1 = fmaxf(mx1, __shfl_xor_sync(0xffffffffu, mx1, 1));
        mx1 = fmaxf(mx1, __shfl_xor_sync(0xffffffffu, mx1, 2));
        float mn0 = fmaxf(mrow0, mx0), mn1 = fmaxf(mrow1, mx1);
        float cr0 = ex2f(mrow0 - mn0), cr1 = ex2f(mrow1 - mn1);
        mrow0 = mn0; mrow1 = mn1;
        lrow0 *= cr0; lrow1 *= cr1;
#pragma unroll
        for (int j = 0; j < 16; ++j) {
            oacc[j][0] *= cr0; oacc[j][1] *= cr0;
            oacc[j][2] *= cr1; oacc[j][3] *= cr1;
        }
        float ls0 = 0.f, ls1 = 0.f;
        uint32_t pah[4][4], pal[4][4];
#pragma unroll
        for (int j = 0; j < 8; ++j) {
            float p0 = ex2f(sacc[j][0] - mn0);
            float p1 = ex2f(sacc[j][1] - mn0);
            float p2 = ex2f(sacc[j][2] - mn1);
            float p3 = ex2f(sacc[j][3] - mn1);
            ls0 += p0 + p1; ls1 += p2 + p3;
            float h0 = __bfloat162float(__float2bfloat16(p0));
            float h1 = __bfloat162float(__float2bfloat16(p1));
            float h2 = __bfloat162float(__float2bfloat16(p2));
            float h3 = __bfloat162float(__float2bfloat16(p3));
            int kt = j >> 1, sl = (j & 1) * 2;
            pah[kt][sl + 0] = pack_bf16(h0, h1);
            pah[kt][sl + 1] = pack_bf16(h2, h3);
            pal[kt][sl + 0] = pack_bf16(p0 - h0, p1 - h1);
            pal[kt][sl + 1] = pack_bf16(p2 - h2, p3 - h3);
        }
        ls0 += __shfl_xor_sync(0xffffffffu, ls0, 1);
        ls0 += __shfl_xor_sync(0xffffffffu, ls0, 2);
        ls1 += __shfl_xor_sync(0xffffffffu, ls1, 1);
        ls1 += __shfl_xor_sync(0xffffffffu, ls1, 2);
        lrow0 += ls0; lrow1 += ls1;

#pragma unroll
        for (int kt = 0; kt < 4; ++kt) {
#pragma unroll
            for (int jd2 = 0; jd2 < 8; ++jd2) {
                uint32_t bh[4], bl[4];
                ldmatrix_x4(bh, kb + AVH + (uint32_t)(jd2 * 16 * 144) + (uint32_t)(kt * 32) + bv_lane);
                ldmatrix_x4(bl, kb + AVL + (uint32_t)(jd2 * 16 * 144) + (uint32_t)(kt * 32) + bv_lane);
                mma16816(oacc[2 * jd2],     pah[kt], &bh[0]);
                mma16816(oacc[2 * jd2],     pal[kt], &bh[0]);
                mma16816(oacc[2 * jd2],     pah[kt], &bl[0]);
                mma16816(oacc[2 * jd2 + 1], pah[kt], &bh[2]);
                mma16816(oacc[2 * jd2 + 1], pal[kt], &bh[2]);
                mma16816(oacc[2 * jd2 + 1], pah[kt], &bl[2]);
            }
        }

        if (more) { asm volatile("cp.async.wait_group 0;" ::: "memory"); }
        __syncthreads();
    }

    // ---- normalize + write fp16-permuted ----
    float inv0 = 1.f / lrow0, inv1 = 1.f / lrow1;
    size_t r0 = (size_t)(b * S + q0 + g) * DIMC;
    size_t r1 = r0 + 8 * DIMC;
    int cbase = h * HDD + tig * 2;
#pragma unroll
    for (int j = 0; j < 16; ++j) {
        int c = cbase + j * 8;
        int p = permch(c);
        __half2 u, v;
        u.x = __float2half(oacc[j][0] * inv0); u.y = __float2half(oacc[j][1] * inv0);
        v.x = __float2half(oacc[j][2] * inv1); v.y = __float2half(oacc[j][3] * inv1);
        *(__half2*)(O + r0 + p) = u;
        *(__half2*)(O + r1 + p) = v;
    }
}

// ---------------- host orchestration ----------------
static void launch_gemm(const __half* A, const __half* B, const float* bias,
                        float* C, __half* Cp, int M, int N, int K, int mode,
                        const float* res, const float* sst, const float* temb,
                        int gidx, int rpb)
{
    dim3 grid(M / 128, N / 128);
    gemm_f16<<<grid, 128, GEMM_SMEM>>>(A, B, bias, C, Cp, N, K, mode,
                                       res, sst, temb, gidx, rpb);
}

extern "C" void kernel_launch(void* const* d_in, const int* in_sizes, int n_in,
                              void* d_out, int out_size)
{
    const float* hs    = (const float*)d_in[0];
    const float* enc   = (const float*)d_in[1];
    const float* temb  = (const float*)d_in[2];
    const float* cosT  = (const float*)d_in[3];
    const float* sinT  = (const float*)d_in[4];
    const float* sst   = (const float*)d_in[5];
    const float* w_qkv = (const float*)d_in[6];
    const float* b_qkv = (const float*)d_in[7];
    const float* rms_q1= (const float*)d_in[8];
    const float* rms_k1= (const float*)d_in[9];
    const float* w_o1  = (const float*)d_in[10];
    const float* b_o1  = (const float*)d_in[11];
    const float* ln2_g = (const float*)d_in[12];
    const float* ln2_b = (const float*)d_in[13];
    const float* w_q2  = (const float*)d_in[14];
    const float* b_q2  = (const float*)d_in[15];
    const float* w_kv2 = (const float*)d_in[16];
    const float* b_kv2 = (const float*)d_in[17];
    const float* rms_q2= (const float*)d_in[18];
    const float* rms_k2= (const float*)d_in[19];
    const float* w_o2  = (const float*)d_in[20];
    const float* b_o2  = (const float*)d_in[21];
    const float* w_ff1 = (const float*)d_in[22];
    const float* b_ff1 = (const float*)d_in[23];
    const float* w_ff2 = (const float*)d_in[24];
    const float* b_ff2 = (const float*)d_in[25];
    float* out = (float*)d_out;

    float *pqkv, *pq, *ph, *pkv;
    __half *px, *pao, *pf, *penc;
    __half *wt0, *wt1, *wt2, *wt3, *wt4, *wt5, *wt6;
    bf16 *pqah, *pqal, *pkah, *pkal, *pvth, *pvtl;
    cudaGetSymbolAddress((void**)&pqkv, g_qkv);
    cudaGetSymbolAddress((void**)&pq,   g_q);
    cudaGetSymbolAddress((void**)&ph,   g_h);
    cudaGetSymbolAddress((void**)&pkv,  g_kv);
    cudaGetSymbolAddress((void**)&px,   g_x);
    cudaGetSymbolAddress((void**)&pao,  g_ao);
    cudaGetSymbolAddress((void**)&pf,   g_f);
    cudaGetSymbolAddress((void**)&penc, g_enc);
    cudaGetSymbolAddress((void**)&wt0, g_wt0);
    cudaGetSymbolAddress((void**)&wt1, g_wt1);
    cudaGetSymbolAddress((void**)&wt2, g_wt2);
    cudaGetSymbolAddress((void**)&wt3, g_wt3);
    cudaGetSymbolAddress((void**)&wt4, g_wt4);
    cudaGetSymbolAddress((void**)&wt5, g_wt5);
    cudaGetSymbolAddress((void**)&wt6, g_wt6);
    cudaGetSymbolAddress((void**)&pqah, g_qah); cudaGetSymbolAddress((void**)&pqal, g_qal);
    cudaGetSymbolAddress((void**)&pkah, g_kah); cudaGetSymbolAddress((void**)&pkal, g_kal);
    cudaGetSymbolAddress((void**)&pvth, g_vth); cudaGetSymbolAddress((void**)&pvtl, g_vtl);

    cudaFuncSetAttribute(gemm_f16, cudaFuncAttributeMaxDynamicSharedMemorySize, GEMM_SMEM);
    cudaFuncSetAttribute(attn_mma, cudaFuncAttributeMaxDynamicSharedMemorySize, ATT_SMEM);

    const float QSCALE = (float)(0.08838834764831845 * 1.4426950408889634); // scale*log2(e)

    convert_kernel<<<3 * DIMC, 256>>>(w_qkv, wt0, DIMC);
    convert_kernel<<<DIMC, 256>>>(w_o1,  wt1, DIMC);
    convert_kernel<<<DIMC, 256>>>(w_q2,  wt2, DIMC);
    convert_kernel<<<2 * DIMC, 256>>>(w_kv2, wt3, DIMC);
    convert_kernel<<<DIMC, 256>>>(w_o2,  wt4, DIMC);
    convert_kernel<<<FFNN, 256>>>(w_ff1, wt5, DIMC);
    convert_kernel<<<DIMC, 256>>>(w_ff2, wt6, FFNN);
    convert_kernel<<<ROWSC, 256>>>(enc, penc, DIMC);

    // 1) x = modLN(h) -> fp16-permuted
    ln_kernel<<<ROWS, 256>>>(hs, px, nullptr, nullptr, sst, temb, 0, 1, SS);
    // 2) qkv = x @ w_qkv^T + b (f32)
    launch_gemm(px, wt0, b_qkv, pqkv, nullptr, ROWS, 3 * DIMC, DIMC, 0,
                nullptr, nullptr, nullptr, 0, SS);
    // 3) q,k = rope(rms(.)) -> bf16 hi/lo ; V^T
    rmsrope_kernel<<<ROWS, 256>>>(pqkv, 3 * DIMC, 0,    pqah, pqal, rms_q1, cosT, sinT, SS, QSCALE);
    rmsrope_kernel<<<ROWS, 256>>>(pqkv, 3 * DIMC, DIMC, pkah, pkal, rms_k1, cosT, sinT, SS, 1.f);
    vtrans_kernel<<<dim3(SS / 32, HH, BB), 256>>>(pqkv, 3 * DIMC, 2 * DIMC, pvth, pvtl, SS);
    // 4) self-attention -> fp16-permuted
    attn_mma<<<dim3(SS / 128, HH, BB), 256, ATT_SMEM>>>(
        pqah, pqal, pkah, pkal, pvth, pvtl, pao, SS, SS);
    // 5) h = hidden + gate_sa * (attn @ w_o1^T + b_o1)
    launch_gemm(pao, wt1, b_o1, ph, nullptr, ROWS, DIMC, DIMC, 2, hs, sst, temb, 2, SS);
    // 6) x = LN(h, g, b)
    ln_kernel<<<ROWS, 256>>>(ph, px, ln2_g, ln2_b, nullptr, nullptr, 0, 0, SS);
    // 7) q2 = rms(x @ w_q2^T + b_q2)
    launch_gemm(px, wt2, b_q2, pq, nullptr, ROWS, DIMC, DIMC, 0,
                nullptr, nullptr, nullptr, 0, SS);
    rms_out_kernel<<<ROWS, 256>>>(pq, DIMC, 0, pqah, pqal, rms_q2, QSCALE);
    // 8) kv = enc @ w_kv2^T + b ; k2 = rms ; v2^T
    launch_gemm(penc, wt3, b_kv2, pkv, nullptr, ROWSC, 2 * DIMC, DIMC, 0,
                nullptr, nullptr, nullptr, 0, SCC);
    rms_out_kernel<<<ROWSC, 256>>>(pkv, 2 * DIMC, 0, pkah, pkal, rms_k2, 1.f);
    vtrans_kernel<<<dim3(SCC / 32, HH, BB), 256>>>(pkv, 2 * DIMC, DIMC, pvth, pvtl, SCC);
    // 9) cross-attention -> fp16-permuted
    attn_mma<<<dim3(SS / 128, HH, BB), 256, ATT_SMEM>>>(
        pqah, pqal, pkah, pkal, pvth, pvtl, pao, SS, SCC);
    // 10) h += attn @ w_o2^T + b_o2
    launch_gemm(pao, wt4, b_o2, ph, nullptr, ROWS, DIMC, DIMC, 1, ph, nullptr, nullptr, 0, SS);
    // 11) x = modLN(h; shift=3, scale=4)
    ln_kernel<<<ROWS, 256>>>(ph, px, nullptr, nullptr, sst, temb, 3, 4, SS);
    // 12) f = gelu(x @ w_ff1^T + b_ff1) -> fp16-permuted
    launch_gemm(px, wt5, b_ff1, nullptr, pf, ROWS, FFNN, DIMC, 3,
                nullptr, nullptr, nullptr, 0, SS);
    // 13) out = h + gate_ff * (f @ w_ff2^T + b_ff2)
    launch_gemm(pf, wt6, b_ff2, out, nullptr, ROWS, DIMC, FFNN, 2, ph, sst, temb, 5, SS);
}

// round 12
// speedup vs baseline: 2.6236x; 1.1659x over previous
#include <cuda_runtime.h>
#include <cuda_bf16.h>
#include <cuda_fp16.h>
#include <math.h>
#include <stdint.h>

#define DIMC 2560
#define BB 2
#define SS 2048
#define SCC 512
#define HH 20
#define HDD 128
#define FFNN 10240
#define EPSF 1e-6f
#define ROWS (BB*SS)      /* 4096 */
#define ROWSC (BB*SCC)    /* 1024 */

typedef __nv_bfloat16 bf16;

// ---------------- scratch (device globals) ----------------
__device__ float g_qkv[(size_t)ROWS*3*DIMC];
__device__ float g_q  [(size_t)ROWS*DIMC];
__device__ float g_h  [(size_t)ROWS*DIMC];
__device__ float g_kv [(size_t)ROWSC*2*DIMC];
__device__ __half g_x  [(size_t)ROWS*DIMC];     // fp16-permuted LN output
__device__ __half g_ao [(size_t)ROWS*DIMC];     // fp16-permuted attention output
__device__ __half g_f  [(size_t)ROWS*FFNN];     // fp16-permuted gelu output
__device__ __half g_enc[(size_t)ROWSC*DIMC];
__device__ __half g_wt0[(size_t)3*DIMC*DIMC];
__device__ __half g_wt1[(size_t)DIMC*DIMC];
__device__ __half g_wt2[(size_t)DIMC*DIMC];
__device__ __half g_wt3[(size_t)2*DIMC*DIMC];
__device__ __half g_wt4[(size_t)DIMC*DIMC];
__device__ __half g_wt5[(size_t)FFNN*DIMC];
__device__ __half g_wt6[(size_t)DIMC*FFNN];
__device__ __half g_qa[(size_t)ROWS*DIMC];
__device__ __half g_ka[(size_t)ROWS*DIMC];
__device__ __half g_vt[(size_t)BB*HH*HDD*SS];

// ---------------- helpers ----------------
__device__ __forceinline__ void cp_async16(uint32_t saddr, const void* gaddr){
    asm volatile("cp.async.cg.shared.global [%0], [%1], 16;" :: "r"(saddr), "l"(gaddr));
}
__device__ __forceinline__ void cp_commit(){ asm volatile("cp.async.commit_group;" ::: "memory"); }
__device__ __forceinline__ uint32_t smem_u32(const void* p){
    uint32_t a; asm("{ .reg .u64 t; cvta.to.shared.u64 t, %1; cvt.u32.u64 %0, t; }" : "=r"(a) : "l"(p)); return a;
}
__device__ __forceinline__ void mma_f16(float* d, const uint32_t* a, const uint32_t* b){
    asm volatile("mma.sync.aligned.m16n8k16.row.col.f32.f16.f16.f32 "
        "{%0,%1,%2,%3}, {%4,%5,%6,%7}, {%8,%9}, {%0,%1,%2,%3};"
        : "+f"(d[0]), "+f"(d[1]), "+f"(d[2]), "+f"(d[3])
        : "r"(a[0]), "r"(a[1]), "r"(a[2]), "r"(a[3]), "r"(b[0]), "r"(b[1]));
}
__device__ __forceinline__ void ldmatrix_x4(uint32_t* r, uint32_t addr){
    asm volatile("ldmatrix.sync.aligned.m8n8.x4.shared.b16 {%0,%1,%2,%3}, [%4];"
        : "=r"(r[0]), "=r"(r[1]), "=r"(r[2]), "=r"(r[3]) : "r"(addr));
}
__device__ __forceinline__ void lds128(uint32_t* r, uint32_t addr){
    asm volatile("ld.shared.v4.b32 {%0,%1,%2,%3}, [%4];"
        : "=r"(r[0]), "=r"(r[1]), "=r"(r[2]), "=r"(r[3]) : "r"(addr));
}
__device__ __forceinline__ float ex2f(float x){
    float y; asm("ex2.approx.f32 %0, %1;" : "=f"(y) : "f"(x)); return y;
}
__device__ __forceinline__ uint32_t pack_h(float a, float b){
    __half2 t; t.x = __float2half(a); t.y = __float2half(b);
    return *(uint32_t*)&t;
}
__device__ __forceinline__ float gelu_tanh(float u){
    return 0.5f * u * (1.f + tanhf(0.7978845608028654f * (u + 0.044715f * u * u * u)));
}
// fp16 K-permutation within each 32-element block
__device__ __forceinline__ int permch(int c){
    int t = (c & 7) >> 1;
    int idx = (c & 1) | (((c >> 3) & 1) << 1) | (((c >> 4) & 1) << 2);
    return (c & ~31) | (t << 3) | idx;
}

// ---------------- weight/encoder convert: f32 -> fp16, K-permuted ----------
__global__ __launch_bounds__(256) void convert_kernel(
    const float* __restrict__ src, __half* __restrict__ dst, int K)
{
    const float* s = src + (size_t)blockIdx.x * K;
    __half* d = dst + (size_t)blockIdx.x * K;
    for (int c = threadIdx.x; c < K; c += 256)
        d[permch(c)] = __float2half(s[c]);
}

// ---------------- LayerNorm -> fp16-permuted ----------------
__global__ __launch_bounds__(256) void ln_kernel(
    const float* __restrict__ x, __half* __restrict__ o,
    const float* __restrict__ gamma, const float* __restrict__ beta,
    const float* __restrict__ sst, const float* __restrict__ temb,
    int shift_idx, int scale_idx, int S)
{
    int row = blockIdx.x;
    int b = row / S;
    const float* xr = x + (size_t)row * DIMC;
    float vals[10];
    float s1 = 0.f, s2 = 0.f;
#pragma unroll
    for (int i = 0; i < 10; ++i) {
        float v = xr[threadIdx.x + i * 256];
        vals[i] = v; s1 += v; s2 += v * v;
    }
#pragma unroll
    for (int o2 = 16; o2 > 0; o2 >>= 1) {
        s1 += __shfl_xor_sync(0xffffffffu, s1, o2);
        s2 += __shfl_xor_sync(0xffffffffu, s2, o2);
    }
    __shared__ float red[16];
    int wid = threadIdx.x >> 5;
    if ((threadIdx.x & 31) == 0) { red[wid] = s1; red[8 + wid] = s2; }
    __syncthreads();
    float ts = 0.f, tq = 0.f;
#pragma unroll
    for (int i = 0; i < 8; ++i) { ts += red[i]; tq += red[8 + i]; }
    float mean = ts * (1.f / DIMC);
    float var  = tq * (1.f / DIMC) - mean * mean;
    float inv  = rsqrtf(var + EPSF);
    size_t ro = (size_t)row * DIMC;
#pragma unroll
    for (int i = 0; i < 10; ++i) {
        int c = threadIdx.x + i * 256;
        float y = (vals[i] - mean) * inv;
        if (sst) {
            float scv = sst[scale_idx * DIMC + c] + temb[((size_t)b * 6 + scale_idx) * DIMC + c];
            float shv = sst[shift_idx * DIMC + c] + temb[((size_t)b * 6 + shift_idx) * DIMC + c];
            y = y * (1.f + scv) + shv;
        } else if (gamma) {
            y = y * gamma[c] + beta[c];
        }
        o[ro + permch(c)] = __float2half(y);
    }
}

// ---------------- RMSNorm + RoPE -> fp16 (scaled) --------------------------
__global__ __launch_bounds__(256) void rmsrope_kernel(
    const float* __restrict__ in, int istride, int ioff,
    __half* __restrict__ o, const float* __restrict__ w,
    const float* __restrict__ cosT, const float* __restrict__ sinT, int S, float scale)
{
    int row = blockIdx.x;
    int s = row % S;
    const float* xr = in + (size_t)row * istride + ioff;
    float vals[10];
    float sq = 0.f;
#pragma unroll
    for (int i = 0; i < 10; ++i) {
        float v = xr[threadIdx.x + i * 256];
        vals[i] = v; sq += v * v;
    }
#pragma unroll
    for (int o2 = 16; o2 > 0; o2 >>= 1) sq += __shfl_xor_sync(0xffffffffu, sq, o2);
    __shared__ float red[8];
    int wid = threadIdx.x >> 5;
    if ((threadIdx.x & 31) == 0) red[wid] = sq;
    __syncthreads();
    float tq = 0.f;
#pragma unroll
    for (int i = 0; i < 8; ++i) tq += red[i];
    float inv = rsqrtf(tq * (1.f / DIMC) + EPSF);
    size_t ro = (size_t)row * DIMC;
#pragma unroll
    for (int i = 0; i < 10; ++i) {
        int c = threadIdx.x + i * 256;
        int d = c & (HDD - 1);
        int pc = (d < 64) ? c + 64 : c - 64;
        float y  = vals[i] * inv * w[c];
        float py = xr[pc]  * inv * w[pc];
        float cv = cosT[(size_t)s * HDD + d];
        float sv = sinT[(size_t)s * HDD + d];
        float val = (y * cv + ((d < 64) ? -py : py) * sv) * scale;
        o[ro + c] = __float2half(val);
    }
}

// ---------------- RMSNorm -> fp16 (scaled) ----------------
__global__ __launch_bounds__(256) void rms_out_kernel(
    const float* __restrict__ in, int istride, int ioff,
    __half* __restrict__ o, const float* __restrict__ w, float scale)
{
    int row = blockIdx.x;
    const float* xr = in + (size_t)row * istride + ioff;
    float vals[10];
    float sq = 0.f;
#pragma unroll
    for (int i = 0; i < 10; ++i) {
        float v = xr[threadIdx.x + i * 256];
        vals[i] = v; sq += v * v;
    }
#pragma unroll
    for (int o2 = 16; o2 > 0; o2 >>= 1) sq += __shfl_xor_sync(0xffffffffu, sq, o2);
    __shared__ float red[8];
    int wid = threadIdx.x >> 5;
    if ((threadIdx.x & 31) == 0) red[wid] = sq;
    __syncthreads();
    float tq = 0.f;
#pragma unroll
    for (int i = 0; i < 8; ++i) tq += red[i];
    float inv = rsqrtf(tq * (1.f / DIMC) + EPSF);
    size_t ro = (size_t)row * DIMC;
#pragma unroll
    for (int i = 0; i < 10; ++i) {
        int c = threadIdx.x + i * 256;
        o[ro + c] = __float2half(vals[i] * inv * w[c] * scale);
    }
}

// ---------------- V transpose: f32 -> fp16 [b,h,d,s] ------------------------
__global__ __launch_bounds__(256) void vtrans_kernel(
    const float* __restrict__ in, int istride, int ioff,
    __half* __restrict__ o, int Skv)
{
    __shared__ float tile[32 * 129];
    int s0 = blockIdx.x * 32;
    int h  = blockIdx.y;
    int b  = blockIdx.z;
    int tid = threadIdx.x;
#pragma unroll
    for (int i = 0; i < 16; ++i) {
        int id = i * 256 + tid;
        int s = id >> 7, d = id & 127;
        tile[s * 129 + d] = in[(size_t)(b * Skv + s0 + s) * istride + ioff + h * HDD + d];
    }
    __syncthreads();
#pragma unroll
    for (int i = 0; i < 16; ++i) {
        int id = i * 256 + tid;
        int d = id >> 5, s = id & 31;
        o[((size_t)((b * HH + h) * HDD + d)) * Skv + s0 + s] = __float2half(tile[s * 129 + d]);
    }
}

// ---------------- FP16 GEMM: 128x128 CTA, 4 warps of 64x64, 3-stage ---------
#define GTILEB (128 * 64)                /* 8192 */
#define GSTAGEB (2 * GTILEB)             /* 16384 */
#define GEMM_SMEM (3 * GSTAGEB)          /* 49152 */

__global__ __launch_bounds__(128, 2) void gemm_f16(
    const __half* __restrict__ A, const __half* __restrict__ B,
    const float* __restrict__ bias,
    float* __restrict__ C, __half* __restrict__ Cp,
    int N, int K, int mode,
    const float* __restrict__ res, const float* __restrict__ sst,
    const float* __restrict__ temb, int gate_idx, int rows_per_batch)
{
    extern __shared__ char smem[];
    const uint32_t sb = smem_u32(smem);
    const int tid = threadIdx.x;
    const int wid = tid >> 5, lane = tid & 31;
    const int wm = wid & 1, wn = wid >> 1;
    const int g = lane >> 2, tig = lane & 3;
    const int mt = blockIdx.x, nt = blockIdx.y;

    const int NIT = K >> 5;
    const char* Ag = (const char*)(A + (size_t)mt * 128 * K);
    const char* Bg = (const char*)(B + (size_t)nt * 128 * K);
    const size_t grb = (size_t)K * 2;

    auto load_tile = [&](int kc, int buf) {
        uint32_t s0 = sb + (uint32_t)buf * GSTAGEB;
        const char* a0 = Ag + (size_t)kc * 64;
        const char* b0 = Bg + (size_t)kc * 64;
#pragma unroll
        for (int i = 0; i < 4; ++i) {
            int idx = i * 128 + tid;
            int r = idx >> 2, c = idx & 3;
            uint32_t sw = (uint32_t)(r * 64 + ((c ^ (r & 3)) << 4));
            cp_async16(s0 + sw, a0 + (size_t)r * grb + c * 16);
        }
#pragma unroll
        for (int i = 0; i < 4; ++i) {
            int idx = i * 128 + tid;
            int r = idx >> 2, c = idx & 3;
            uint32_t sw = (uint32_t)(r * 64 + ((c ^ (r & 3)) << 4));
            cp_async16(s0 + GTILEB + sw, b0 + (size_t)r * grb + c * 16);
        }
        cp_commit();
    };

    load_tile(0, 0);
    if (NIT > 1) load_tile(1, 1);

    float acc[4][8][4];
#pragma unroll
    for (int mi = 0; mi < 4; ++mi)
#pragma unroll
        for (int ni = 0; ni < 8; ++ni)
#pragma unroll
            for (int j = 0; j < 4; ++j) acc[mi][ni][j] = 0.f;

    const uint32_t swz = (uint32_t)((tig ^ (g & 3)) << 4);

    int buf = 0;
    for (int it = 0; it < NIT; ++it) {
        asm volatile("cp.async.wait_group 1;" ::: "memory");
        __syncthreads();
        if (it + 2 < NIT) {
            int nb = buf + 2; if (nb >= 3) nb -= 3;
            load_tile(it + 2, nb);
        }
        uint32_t su = sb + (uint32_t)buf * GSTAGEB;
        uint32_t am[4][8];
#pragma unroll
        for (int mi = 0; mi < 4; ++mi) {
            int R = wm * 64 + mi * 16 + g;
            lds128(&am[mi][0], su + (uint32_t)(R * 64) + swz);
            lds128(&am[mi][4], su + (uint32_t)((R + 8) * 64) + swz);
        }
        uint32_t bm[8][4];
#pragma unroll
        for (int nj = 0; nj < 8; ++nj) {
            int Rn = wn * 64 + nj * 8 + g;
            lds128(&bm[nj][0], su + GTILEB + (uint32_t)(Rn * 64) + swz);
        }
#pragma unroll
        for (int mi = 0; mi < 4; ++mi) {
            uint32_t a0[4] = {am[mi][0], am[mi][4], am[mi][1], am[mi][5]};
            uint32_t a1[4] = {am[mi][2], am[mi][6], am[mi][3], am[mi][7]};
#pragma unroll
            for (int nj = 0; nj < 8; ++nj) {
                mma_f16(acc[mi][nj], a0, &bm[nj][0]);
                mma_f16(acc[mi][nj], a1, &bm[nj][2]);
            }
        }
        ++buf; if (buf >= 3) buf = 0;
    }

#pragma unroll
    for (int mi = 0; mi < 4; ++mi) {
#pragma unroll
        for (int half = 0; half < 2; ++half) {
            int m = mt * 128 + wm * 64 + mi * 16 + g + half * 8;
            size_t rowb = (size_t)m * N;
#pragma unroll
            for (int ni = 0; ni < 8; ++ni) {
                int n = nt * 128 + wn * 64 + ni * 8 + tig * 2;
                float v0 = acc[mi][ni][half * 2 + 0] + bias[n];
                float v1 = acc[mi][ni][half * 2 + 1] + bias[n + 1];
                if (mode == 3) {
                    int p = permch(n);
                    __half2 hv; hv.x = __float2half(gelu_tanh(v0)); hv.y = __float2half(gelu_tanh(v1));
                    *(__half2*)(Cp + rowb + p) = hv;
                } else if (mode == 2) {
                    int bb = m / rows_per_batch;
                    float g0 = sst[(size_t)gate_idx * N + n]     + temb[((size_t)bb * 6 + gate_idx) * N + n];
                    float g1 = sst[(size_t)gate_idx * N + n + 1] + temb[((size_t)bb * 6 + gate_idx) * N + n + 1];
                    float2 rv = *(const float2*)(res + rowb + n);
                    float2 w; w.x = rv.x + g0 * v0; w.y = rv.y + g1 * v1;
                    *(float2*)(C + rowb + n) = w;
                } else if (mode == 1) {
                    float2 rv = *(const float2*)(res + rowb + n);
                    float2 w; w.x = rv.x + v0; w.y = rv.y + v1;
                    *(float2*)(C + rowb + n) = w;
                } else {
                    float2 w; w.x = v0; w.y = v1;
                    *(float2*)(C + rowb + n) = w;
                }
            }
        }
    }
}

// ---------------- fp16 flash attention (single-pass) ------------------------
// K smem rows 272B pitch, V^T rows 144B pitch (proven conflict-free).
#define AK 0
#define AV 17408
#define ASTG 35840
#define ATT_SMEM (2 * ASTG)   /* 71680 */

__global__ __launch_bounds__(256) void attn_mma(
    const __half* __restrict__ q, const __half* __restrict__ k,
    const __half* __restrict__ vt,
    __half* __restrict__ O,
    int S, int Skv)
{
    extern __shared__ char sm[];
    const uint32_t sb = smem_u32(sm);
    const int tid = threadIdx.x;
    const int wid = tid >> 5, lane = tid & 31;
    const int g = lane >> 2, tig = lane & 3;
    const int h = blockIdx.y, b = blockIdx.z;
    const int q0 = blockIdx.x * 128 + wid * 16;

    // ---- Q fragments in registers ----
    const __half* qb = q + ((size_t)(b * S + q0 + g) * DIMC + h * HDD + tig * 2);
    uint32_t qf[8][4];
#pragma unroll
    for (int kc = 0; kc < 8; ++kc) {
        qf[kc][0] = *(const uint32_t*)(qb + kc * 16);
        qf[kc][1] = *(const uint32_t*)(qb + 8 * DIMC + kc * 16);
        qf[kc][2] = *(const uint32_t*)(qb + kc * 16 + 8);
        qf[kc][3] = *(const uint32_t*)(qb + 8 * DIMC + kc * 16 + 8);
    }

    float oacc[16][4];
#pragma unroll
    for (int j = 0; j < 16; ++j)
#pragma unroll
        for (int i = 0; i < 4; ++i) oacc[j][i] = 0.f;
    float mrow0 = -1e30f, mrow1 = -1e30f, lrow0 = 0.f, lrow1 = 0.f;

    const int nkt = Skv >> 6;

    auto stage = [&](int t) {
        uint32_t s0 = sb + (uint32_t)(t & 1) * ASTG;
        const char* kg = (const char*)(k + ((size_t)(b * Skv + t * 64) * DIMC + h * HDD));
#pragma unroll
        for (int i = 0; i < 4; ++i) {
            int id = i * 256 + tid;
            int r = id >> 4, c = id & 15;
            cp_async16(s0 + AK + (uint32_t)(r * 272 + c * 16), kg + (size_t)r * DIMC * 2 + c * 16);
        }
        const char* vg = (const char*)(vt + ((size_t)((b * HH + h) * HDD) * Skv + t * 64));
#pragma unroll
        for (int i = 0; i < 4; ++i) {
            int id = i * 256 + tid;
            int r = id >> 3, c = id & 7;
            cp_async16(s0 + AV + (uint32_t)(r * 144 + c * 16), vg + (size_t)r * Skv * 2 + c * 16);
        }
        cp_commit();
    };

    const uint32_t bk_lane = (uint32_t)(((lane & 7) + ((lane >> 4) << 3)) * 272 + (((lane >> 3) & 1) << 4));
    const uint32_t bv_lane = (uint32_t)(((lane & 7) + ((lane >> 4) << 3)) * 144 + (((lane >> 3) & 1) << 4));

    stage(0);
    asm volatile("cp.async.wait_group 0;" ::: "memory");
    __syncthreads();

    for (int t = 0; t < nkt; ++t) {
        bool more = (t + 1 < nkt);
        if (more) stage(t + 1);

        uint32_t kb = sb + (uint32_t)(t & 1) * ASTG;

        // ---- QK^T ----
        float sacc[8][4];
#pragma unroll
        for (int j = 0; j < 8; ++j)
#pragma unroll
            for (int i = 0; i < 4; ++i) sacc[j][i] = 0.f;
#pragma unroll
        for (int kc = 0; kc < 8; ++kc) {
#pragma unroll
            for (int j2 = 0; j2 < 4; ++j2) {
                uint32_t bh[4];
                ldmatrix_x4(bh, kb + AK + (uint32_t)(j2 * 16 * 272) + (uint32_t)(kc * 32) + bk_lane);
                mma_f16(sacc[2 * j2],     qf[kc], &bh[0]);
                mma_f16(sacc[2 * j2 + 1], qf[kc], &bh[2]);
            }
        }

        // ---- online softmax ----
        float mx0 = -1e30f, mx1 = -1e30f;
#pragma unroll
        for (int j = 0; j < 8; ++j) {
            mx0 = fmaxf(mx0, fmaxf(sacc[j][0], sacc[j][1]));
            mx1 = fmaxf(mx1, fmaxf(sacc[j][2], sacc[j][3]));
        }
        mx0 = fmaxf(mx0, __shfl_xor_sync(0xffffffffu, mx0, 1));
        mx0 = fmaxf(mx0, __shfl_xor_sync(0xffffffffu, mx0, 2));
        mx1 = fmaxf(mx1, __shfl_xor_sync(0xffffffffu, mx1, 1));
        mx1 = fmaxf(mx1, __shfl_xor_sync(0xffffffffu, mx1, 2));
        float mn0 = fmaxf(mrow0, mx0), mn1 = fmaxf(mrow1, mx1);
        float cr0 = ex2f(mrow0 - mn0), cr1 = ex2f(mrow1 - mn1);
        mrow0 = mn0; mrow1 = mn1;
        lrow0 *= cr0; lrow1 *= cr1;
#pragma unroll
        for (int j = 0; j < 16; ++j) {
            oacc[j][0] *= cr0; oacc[j][1] *= cr0;
            oacc[j][2] *= cr1; oacc[j][3] *= cr1;
        }
        float ls0 = 0.f, ls1 = 0.f;
        uint32_t pa[4][4];
#pragma unroll
        for (int j = 0; j < 8; ++j) {
            float p0 = ex2f(sacc[j][0] - mn0);
            float p1 = ex2f(sacc[j][1] - mn0);
            float p2 = ex2f(sacc[j][2] - mn1);
            float p3 = ex2f(sacc[j][3] - mn1);
            ls0 += p0 + p1; ls1 += p2 + p3;
            int kt = j >> 1, sl = (j & 1) * 2;
            pa[kt][sl + 0] = pack_h(p0, p1);
            pa[kt][sl + 1] = pack_h(p2, p3);
        }
        ls0 += __shfl_xor_sync(0xffffffffu, ls0, 1);
        ls0 += __shfl_xor_sync(0xffffffffu, ls0, 2);
        ls1 += __shfl_xor_sync(0xffffffffu, ls1, 1);
        ls1 += __shfl_xor_sync(0xffffffffu, ls1, 2);
        lrow0 += ls0; lrow1 += ls1;

        // ---- P*V ----
#pragma unroll
        for (int kt = 0; kt < 4; ++kt) {
#pragma unroll
            for (int jd2 = 0; jd2 < 8; ++jd2) {
                uint32_t bv[4];
                ldmatrix_x4(bv, kb + AV + (uint32_t)(jd2 * 16 * 144) + (uint32_t)(kt * 32) + bv_lane);
                mma_f16(oacc[2 * jd2],     pa[kt], &bv[0]);
                mma_f16(oacc[2 * jd2 + 1], pa[kt], &bv[2]);
            }
        }

        if (more) { asm volatile("cp.async.wait_group 0;" ::: "memory"); }
        __syncthreads();
    }

    // ---- normalize + write fp16-permuted ----
    float inv0 = 1.f / lrow0, inv1 = 1.f / lrow1;
    size_t r0 = (size_t)(b * S + q0 + g) * DIMC;
    size_t r1 = r0 + 8 * DIMC;
    int cbase = h * HDD + tig * 2;
#pragma unroll
    for (int j = 0; j < 16; ++j) {
        int c = cbase + j * 8;
        int p = permch(c);
        __half2 u, v;
        u.x = __float2half(oacc[j][0] * inv0); u.y = __float2half(oacc[j][1] * inv0);
        v.x = __float2half(oacc[j][2] * inv1); v.y = __float2half(oacc[j][3] * inv1);
        *(__half2*)(O + r0 + p) = u;
        *(__half2*)(O + r1 + p) = v;
    }
}

// ---------------- host orchestration ----------------
static void launch_gemm(const __half* A, const __half* B, const float* bias,
                        float* C, __half* Cp, int M, int N, int K, int mode,
                        const float* res, const float* sst, const float* temb,
                        int gidx, int rpb)
{
    dim3 grid(M / 128, N / 128);
    gemm_f16<<<grid, 128, GEMM_SMEM>>>(A, B, bias, C, Cp, N, K, mode,
                                       res, sst, temb, gidx, rpb);
}

extern "C" void kernel_launch(void* const* d_in, const int* in_sizes, int n_in,
                              void* d_out, int out_size)
{
    const float* hs    = (const float*)d_in[0];
    const float* enc   = (const float*)d_in[1];
    const float* temb  = (const float*)d_in[2];
    const float* cosT  = (const float*)d_in[3];
    const float* sinT  = (const float*)d_in[4];
    const float* sst   = (const float*)d_in[5];
    const float* w_qkv = (const float*)d_in[6];
    const float* b_qkv = (const float*)d_in[7];
    const float* rms_q1= (const float*)d_in[8];
    const float* rms_k1= (const float*)d_in[9];
    const float* w_o1  = (const float*)d_in[10];
    const float* b_o1  = (const float*)d_in[11];
    const float* ln2_g = (const float*)d_in[12];
    const float* ln2_b = (const float*)d_in[13];
    const float* w_q2  = (const float*)d_in[14];
    const float* b_q2  = (const float*)d_in[15];
    const float* w_kv2 = (const float*)d_in[16];
    const float* b_kv2 = (const float*)d_in[17];
    const float* rms_q2= (const float*)d_in[18];
    const float* rms_k2= (const float*)d_in[19];
    const float* w_o2  = (const float*)d_in[20];
    const float* b_o2  = (const float*)d_in[21];
    const float* w_ff1 = (const float*)d_in[22];
    const float* b_ff1 = (const float*)d_in[23];
    const float* w_ff2 = (const float*)d_in[24];
    const float* b_ff2 = (const float*)d_in[25];
    float* out = (float*)d_out;

    float *pqkv, *pq, *ph, *pkv;
    __half *px, *pao, *pf, *penc;
    __half *wt0, *wt1, *wt2, *wt3, *wt4, *wt5, *wt6;
    __half *pqa, *pka, *pvt;
    cudaGetSymbolAddress((void**)&pqkv, g_qkv);
    cudaGetSymbolAddress((void**)&pq,   g_q);
    cudaGetSymbolAddress((void**)&ph,   g_h);
    cudaGetSymbolAddress((void**)&pkv,  g_kv);
    cudaGetSymbolAddress((void**)&px,   g_x);
    cudaGetSymbolAddress((void**)&pao,  g_ao);
    cudaGetSymbolAddress((void**)&pf,   g_f);
    cudaGetSymbolAddress((void**)&penc, g_enc);
    cudaGetSymbolAddress((void**)&wt0, g_wt0);
    cudaGetSymbolAddress((void**)&wt1, g_wt1);
    cudaGetSymbolAddress((void**)&wt2, g_wt2);
    cudaGetSymbolAddress((void**)&wt3, g_wt3);
    cudaGetSymbolAddress((void**)&wt4, g_wt4);
    cudaGetSymbolAddress((void**)&wt5, g_wt5);
    cudaGetSymbolAddress((void**)&wt6, g_wt6);
    cudaGetSymbolAddress((void**)&pqa, g_qa);
    cudaGetSymbolAddress((void**)&pka, g_ka);
    cudaGetSymbolAddress((void**)&pvt, g_vt);

    cudaFuncSetAttribute(gemm_f16, cudaFuncAttributeMaxDynamicSharedMemorySize, GEMM_SMEM);
    cudaFuncSetAttribute(attn_mma, cudaFuncAttributeMaxDynamicSharedMemorySize, ATT_SMEM);

    const float QSCALE = (float)(0.08838834764831845 * 1.4426950408889634); // scale*log2(e)

    convert_kernel<<<3 * DIMC, 256>>>(w_qkv, wt0, DIMC);
    convert_kernel<<<DIMC, 256>>>(w_o1,  wt1, DIMC);
    convert_kernel<<<DIMC, 256>>>(w_q2,  wt2, DIMC);
    convert_kernel<<<2 * DIMC, 256>>>(w_kv2, wt3, DIMC);
    convert_kernel<<<DIMC, 256>>>(w_o2,  wt4, DIMC);
    convert_kernel<<<FFNN, 256>>>(w_ff1, wt5, DIMC);
    convert_kernel<<<DIMC, 256>>>(w_ff2, wt6, FFNN);
    convert_kernel<<<ROWSC, 256>>>(enc, penc, DIMC);

    // 1) x = modLN(h) -> fp16-permuted
    ln_kernel<<<ROWS, 256>>>(hs, px, nullptr, nullptr, sst, temb, 0, 1, SS);
    // 2) qkv = x @ w_qkv^T + b (f32)
    launch_gemm(px, wt0, b_qkv, pqkv, nullptr, ROWS, 3 * DIMC, DIMC, 0,
                nullptr, nullptr, nullptr, 0, SS);
    // 3) q,k = rope(rms(.)) -> fp16 ; V^T fp16
    rmsrope_kernel<<<ROWS, 256>>>(pqkv, 3 * DIMC, 0,    pqa, rms_q1, cosT, sinT, SS, QSCALE);
    rmsrope_kernel<<<ROWS, 256>>>(pqkv, 3 * DIMC, DIMC, pka, rms_k1, cosT, sinT, SS, 1.f);
    vtrans_kernel<<<dim3(SS / 32, HH, BB), 256>>>(pqkv, 3 * DIMC, 2 * DIMC, pvt, SS);
    // 4) self-attention -> fp16-permuted
    attn_mma<<<dim3(SS / 128, HH, BB), 256, ATT_SMEM>>>(pqa, pka, pvt, pao, SS, SS);
    // 5) h = hidden + gate_sa * (attn @ w_o1^T + b_o1)
    launch_gemm(pao, wt1, b_o1, ph, nullptr, ROWS, DIMC, DIMC, 2, hs, sst, temb, 2, SS);
    // 6) x = LN(h, g, b)
    ln_kernel<<<ROWS, 256>>>(ph, px, ln2_g, ln2_b, nullptr, nullptr, 0, 0, SS);
    // 7) q2 = rms(x @ w_q2^T + b_q2)
    launch_gemm(px, wt2, b_q2, pq, nullptr, ROWS, DIMC, DIMC, 0,
                nullptr, nullptr, nullptr, 0, SS);
    rms_out_kernel<<<ROWS, 256>>>(pq, DIMC, 0, pqa, rms_q2, QSCALE);
    // 8) kv = enc @ w_kv2^T + b ; k2 = rms ; v2^T
    launch_gemm(penc, wt3, b_kv2, pkv, nullptr, ROWSC, 2 * DIMC, DIMC, 0,
                nullptr, nullptr, nullptr, 0, SCC);
    rms_out_kernel<<<ROWSC, 256>>>(pkv, 2 * DIMC, 0, pka, rms_k2, 1.f);
    vtrans_kernel<<<dim3(SCC / 32, HH, BB), 256>>>(pkv, 2 * DIMC, DIMC, pvt, SCC);
    // 9) cross-attention -> fp16-permuted
    attn_mma<<<dim3(SS / 128, HH, BB), 256, ATT_SMEM>>>(pqa, pka, pvt, pao, SS, SCC);
    // 10) h += attn @ w_o2^T + b_o2
    launch_gemm(pao, wt4, b_o2, ph, nullptr, ROWS, DIMC, DIMC, 1, ph, nullptr, nullptr, 0, SS);
    // 11) x = modLN(h; shift=3, scale=4)
    ln_kernel<<<ROWS, 256>>>(ph, px, nullptr, nullptr, sst, temb, 3, 4, SS);
    // 12) f = gelu(x @ w_ff1^T + b_ff1) -> fp16-permuted
    launch_gemm(px, wt5, b_ff1, nullptr, pf, ROWS, FFNN, DIMC, 3,
                nullptr, nullptr, nullptr, 0, SS);
    // 13) out = h + gate_ff * (f @ w_ff2^T + b_ff2)
    launch_gemm(pf, wt6, b_ff2, out, nullptr, ROWS, DIMC, FFNN, 2, ph, sst, temb, 5, SS);
}